// round 3
// baseline (speedup 1.0000x reference)
#include <cuda_runtime.h>

#define Tn   720
#define Bn   512
#define INn  6
#define Hn   128
#define OUTn 3
#define HORn 360
#define G4n  512          // 4*H
#define NBLK 148
#define NTHR 256

typedef unsigned long long ull;

struct Params {
    const float* x;
    const float* wih[6];   // e0f,e0b,e1f,e1b,d0,d1
    const float* whh[6];
    const float* bih[6];
    const float* bhh[6];
    const float* brh_W; const float* brh_b;
    const float* brc_W; const float* brc_b;
    const float* out_W; const float* out_b;
    const float* start;
    float* out;
};

// ---------------- scratch (device globals; no allocation allowed) ----------------
__device__ float g_y0[(size_t)Tn * Bn * 2 * Hn];      // encoder layer0 outputs [t][b][256]
__device__ float g_wpH[6][Hn][G4n];                   // packed Whh: [k][j*4+gate]
__device__ float g_wpA[6][256][G4n];                  // packed Wih: [k][j*4+gate] (max K_in=256)
__device__ float g_bias[6][G4n];                      // bih+bhh packed [j*4+gate]
__device__ float g_h[2][6][Bn][Hn];                   // double-buffered hidden state per stream
__device__ float g_c[6][Bn][Hn];                      // cell state (in-place)
__device__ float g_xin[Bn * OUTn];                    // decoder autoregressive input
__device__ unsigned g_barcnt = 0;
__device__ unsigned g_bargen = 0;

// ---------------- grid barrier (148 co-resident blocks) ----------------
__device__ __forceinline__ void gbar() {
    __syncthreads();
    if (threadIdx.x == 0) {
        volatile unsigned* vg = &g_bargen;
        unsigned gen = *vg;
        __threadfence();
        if (atomicAdd(&g_barcnt, 1u) == NBLK - 1) {
            g_barcnt = 0;
            __threadfence();
            *vg = gen + 1;
        } else {
            while (*vg == gen) { __nanosleep(32); }
        }
        __threadfence();
    }
    __syncthreads();
}

// ---------------- fast activations (rel err ~1e-6, fine vs 1e-3 gate) ----------------
__device__ __forceinline__ float sigf(float x) {
    return __fdividef(1.f, 1.f + __expf(-x));
}
__device__ __forceinline__ float tanhfast(float x) {
    return 1.f - __fdividef(2.f, __expf(2.f * x) + 1.f);
}

// ---------------- fused LSTM cell tile ----------------
// Tile: 32 b-rows x JW hidden-units. Each thread owns (j, NB b-rows) and computes
// all 4 gate pre-activations (i,f,g,o) via packed f32x2 FMA, then the gate update.
// g = bias + A @ WihP + h @ WhhP ; c' = sig(f)*c + sig(i)*tanh(g) ; h' = sig(o)*tanh(c')
template<int JW>
__device__ void lstm_tile(float* smem, int st, int b0, int j0,
                          const float* __restrict__ A, long aStr, long aOff, int Kin,
                          const float* __restrict__ hsrc, float* __restrict__ hdst,
                          float* __restrict__ cst, float* __restrict__ yout)
{
    constexpr int NB = (32 * JW) / NTHR;     // b-rows per thread: 4 (JW=32) or 2 (JW=16)
    float* s_src = smem;                     // [32][64]   staged activations
    float* s_w   = smem + 32 * 64;           // [64][JW*4] staged packed weights

    const int tid  = threadIdx.x;
    const int jj   = tid % JW;
    const int bsub = tid / JW;
    const int jgl  = j0 + jj;

    ull accL[NB], accH[NB];                  // packed (i,f) and (g,o) accumulators
    {
        const float* bb = &g_bias[st][jgl * 4];
        ull bL = *(const ull*)bb;
        ull bH = *(const ull*)(bb + 2);
#pragma unroll
        for (int i = 0; i < NB; i++) { accL[i] = bL; accH[i] = bH; }
    }

#pragma unroll 1
    for (int seg = 0; seg < 2; seg++) {
        const float* S  = seg ? hsrc : A;
        long str        = seg ? (long)Hn : aStr;
        long off        = seg ? 0L : aOff;
        const float* W  = seg ? &g_wpH[st][0][0] : &g_wpA[st][0][0];
        int K           = seg ? Hn : Kin;
        const int wcols = JW * 4;

        for (int k0 = 0; k0 < K; k0 += 64) {
            int kc = (K - k0 < 64) ? (K - k0) : 64;
            __syncthreads();
            for (int idx = tid; idx < 32 * kc; idx += NTHR) {
                int bl = idx / kc, kk = idx - bl * kc;
                s_src[bl * 64 + kk] = S[(long)(b0 + bl) * str + off + k0 + kk];
            }
            for (int idx = tid; idx < kc * wcols; idx += NTHR) {
                int kk = idx / wcols, c = idx - kk * wcols;
                s_w[kk * wcols + c] = W[(long)(k0 + kk) * G4n + j0 * 4 + c];
            }
            __syncthreads();
#pragma unroll 4
            for (int kk = 0; kk < kc; kk++) {
                const ull* wp = (const ull*)&s_w[kk * wcols + jj * 4];
                ull wL = wp[0], wH = wp[1];
#pragma unroll
                for (int i = 0; i < NB; i++) {
                    float a = s_src[(bsub * NB + i) * 64 + kk];
                    ull a2;
                    asm("mov.b64 %0,{%1,%1};" : "=l"(a2) : "f"(a));
                    asm("fma.rn.f32x2 %0,%1,%2,%0;" : "+l"(accL[i]) : "l"(a2), "l"(wL));
                    asm("fma.rn.f32x2 %0,%1,%2,%0;" : "+l"(accH[i]) : "l"(a2), "l"(wH));
                }
            }
        }
    }

    // gate update — this thread exclusively owns (b, jgl)
#pragma unroll
    for (int i = 0; i < NB; i++) {
        float gi, gf, gg, go;
        asm("mov.b64 {%0,%1},%2;" : "=f"(gi), "=f"(gf) : "l"(accL[i]));
        asm("mov.b64 {%0,%1},%2;" : "=f"(gg), "=f"(go) : "l"(accH[i]));
        int b = b0 + bsub * NB + i;
        long ci = (long)b * Hn + jgl;
        float cold = cst[ci];
        float cn = sigf(gf) * cold + sigf(gi) * tanhfast(gg);
        float hn = sigf(go) * tanhfast(cn);
        cst[ci]  = cn;
        hdst[ci] = hn;
        if (yout) yout[(long)b * (2 * Hn) + jgl] = hn;
    }
}

// ---------------- the persistent kernel ----------------
__global__ void __launch_bounds__(NTHR, 1) orbit_kernel(Params P)
{
    __shared__ float smem[32 * 64 + 64 * 128];   // 40 KB
    const int tid  = threadIdx.x;
    const int gtid = blockIdx.x * NTHR + tid;
    const int gstr = NBLK * NTHR;

    // ===== Phase 0: pack weights [4H x K] -> [K][j*4+gate], biases; zero enc states =====
    {
        const int KIN[6] = {INn, INn, 2 * Hn, 2 * Hn, OUTn, Hn};
#pragma unroll 1
        for (int s6 = 0; s6 < 6; s6++) {
            const float* whh = P.whh[s6];
            for (int e = gtid; e < Hn * G4n; e += gstr) {
                int k = e >> 9, col = e & 511;
                int j = col >> 2, g = col & 3;
                g_wpH[s6][k][col] = whh[(g * Hn + j) * Hn + k];
            }
            int kin = KIN[s6];
            const float* wih = P.wih[s6];
            for (int e = gtid; e < kin * G4n; e += gstr) {
                int k = e >> 9, col = e & 511;
                int j = col >> 2, g = col & 3;
                g_wpA[s6][k][col] = wih[(g * Hn + j) * kin + k];
            }
            const float* bi = P.bih[s6];
            const float* bh = P.bhh[s6];
            for (int e = gtid; e < G4n; e += gstr) {
                int j = e >> 2, g = e & 3;
                g_bias[s6][e] = bi[g * Hn + j] + bh[g * Hn + j];
            }
        }
        float* h0 = &g_h[0][0][0][0];
        float* c0 = &g_c[0][0][0];
        for (int e = gtid; e < 4 * Bn * Hn; e += gstr) { h0[e] = 0.f; c0[e] = 0.f; }
    }
    gbar();

    // ===== Phase 1/2: encoder layers 0 and 1 (fwd & bwd run concurrently per step) =====
#pragma unroll 1
    for (int layer = 0; layer < 2; layer++) {
#pragma unroll 1
        for (int s = 0; s < Tn; s++) {
            int cur = s & 1, nxt = cur ^ 1;
            int tl = blockIdx.x;
            if (tl < 128) {
                int dir = tl >> 6;
                int rem = tl & 63;
                int b0  = (rem >> 2) * 32;
                int j0  = (rem & 3) * 32;
                int st  = layer * 2 + dir;
                int t   = dir ? (Tn - 1 - s) : s;
                if (layer == 0) {
                    lstm_tile<32>(smem, st, b0, j0,
                        P.x, (long)Tn * INn, (long)t * INn, INn,
                        &g_h[cur][st][0][0], &g_h[nxt][st][0][0], &g_c[st][0][0],
                        g_y0 + (size_t)t * Bn * 2 * Hn + dir * Hn);
                } else {
                    lstm_tile<32>(smem, st, b0, j0,
                        g_y0 + (size_t)t * Bn * 2 * Hn, (long)(2 * Hn), 0L, 2 * Hn,
                        &g_h[cur][st][0][0], &g_h[nxt][st][0][0], &g_c[st][0][0],
                        nullptr);
                }
            }
            gbar();
        }
    }

    // ===== Phase 3: bridge (h_dec/c_dec) + start token =====
    {
        // cells: typ(2) x layer(2) x b(512) x j(128) = 2^18
        for (int idx = gtid; idx < (1 << 18); idx += gstr) {
            int j   = idx & (Hn - 1);
            int b   = (idx >> 7) & (Bn - 1);
            int l   = (idx >> 16) & 1;
            int typ = idx >> 17;
            const float* W    = typ ? P.brc_W : P.brh_W;
            const float* bias = typ ? P.brc_b : P.brh_b;
            const float* srcF = typ ? &g_c[2 * l][0][0] : &g_h[0][2 * l][0][0];
            const float* srcB = typ ? &g_c[2 * l + 1][0][0] : &g_h[0][2 * l + 1][0][0];
            const float* wr = &W[j * 2 * Hn];
            float acc = bias[j];
#pragma unroll 4
            for (int k = 0; k < Hn; k++) acc += srcF[b * Hn + k] * wr[k];
#pragma unroll 4
            for (int k = 0; k < Hn; k++) acc += srcB[b * Hn + k] * wr[Hn + k];
            if (typ) g_c[4 + l][b][j] = acc;
            else     g_h[0][4 + l][b][j] = acc;
        }
        for (int idx = gtid; idx < Bn * OUTn; idx += gstr)
            g_xin[idx] = P.start[idx % OUTn];
    }
    gbar();

    // ===== Phase 4: autoregressive decoder =====
#pragma unroll 1
    for (int s = 0; s < HORn; s++) {
        int cur = s & 1, nxt = cur ^ 1;
        int tl = blockIdx.x;
        int b0 = 0, j0 = 0;
        if (tl < 128) { b0 = (tl >> 3) * 32; j0 = (tl & 7) * 16; }

        // cell 0: input = previous prediction (K=3) + h (K=128)
        if (tl < 128)
            lstm_tile<16>(smem, 4, b0, j0, g_xin, (long)OUTn, 0L, OUTn,
                          &g_h[cur][4][0][0], &g_h[nxt][4][0][0], &g_c[4][0][0], nullptr);
        gbar();

        // cell 1: input = cell0's new h (K=128) + own h (K=128)
        if (tl < 128)
            lstm_tile<16>(smem, 5, b0, j0, &g_h[nxt][4][0][0], (long)Hn, 0L, Hn,
                          &g_h[cur][5][0][0], &g_h[nxt][5][0][0], &g_c[5][0][0], nullptr);
        gbar();

        // prediction head + autoregressive feedback
        if (tl < 6) {
            int idx = tl * NTHR + tid;          // 0..1535 = 512*3
            int b = idx / OUTn, o = idx - b * OUTn;
            const float* hp = &g_h[nxt][5][b][0];
            const float* wp = &P.out_W[o * Hn];
            float acc = P.out_b[o];
#pragma unroll 8
            for (int k = 0; k < Hn; k++) acc += hp[k] * wp[k];
            P.out[(size_t)b * HORn * OUTn + (size_t)s * OUTn + o] = acc;
            g_xin[b * OUTn + o] = acc;
        }
        gbar();
    }
}

// ---------------- launch ----------------
extern "C" void kernel_launch(void* const* d_in, const int* in_sizes, int n_in,
                              void* d_out, int out_size)
{
    (void)in_sizes; (void)n_in; (void)out_size;
    Params P;
    P.x = (const float*)d_in[0];
    const int base[6] = {1, 5, 9, 13, 21, 25};   // e0f,e0b,e1f,e1b,d0,d1
    for (int i = 0; i < 6; i++) {
        P.wih[i] = (const float*)d_in[base[i] + 0];
        P.whh[i] = (const float*)d_in[base[i] + 1];
        P.bih[i] = (const float*)d_in[base[i] + 2];
        P.bhh[i] = (const float*)d_in[base[i] + 3];
    }
    P.brh_W = (const float*)d_in[17];
    P.brh_b = (const float*)d_in[18];
    P.brc_W = (const float*)d_in[19];
    P.brc_b = (const float*)d_in[20];
    P.out_W = (const float*)d_in[29];
    P.out_b = (const float*)d_in[30];
    P.start = (const float*)d_in[31];
    P.out   = (float*)d_out;

    orbit_kernel<<<NBLK, NTHR>>>(P);
}

// round 4
// speedup vs baseline: 1.0021x; 1.0021x over previous
#include <cuda_runtime.h>

#define Tn   720
#define Bn   512
#define INn  6
#define Hn   128
#define OUTn 3
#define HORn 360
#define G4n  512          // 4*H
#define NBLK 148
#define NTHR 256

typedef unsigned long long ull;

struct Params {
    const float* x;
    const float* wih[6];   // e0f,e0b,e1f,e1b,d0,d1
    const float* whh[6];
    const float* bih[6];
    const float* bhh[6];
    const float* brh_W; const float* brh_b;
    const float* brc_W; const float* brc_b;
    const float* out_W; const float* out_b;
    const float* start;
    float* out;
};

// ---------------- scratch (device globals; no allocation allowed) ----------------
__device__ float g_y0[(size_t)Tn * Bn * 2 * Hn];      // encoder layer0 outputs [t][b][256]
__device__ float g_wpH[6][Hn][G4n];                   // packed Whh: [k][j*4+gate]
__device__ float g_wpA[6][256][G4n];                  // packed Wih: [k][j*4+gate] (max K_in=256)
__device__ float g_bias[6][G4n];                      // bih+bhh packed [j*4+gate]
__device__ float g_h[2][6][Bn][Hn];                   // double-buffered hidden state per stream
__device__ float g_c[6][Bn][Hn];                      // cell state (in-place)
__device__ float g_xin[Bn * OUTn];                    // decoder autoregressive input
__device__ unsigned g_barcnt = 0;
__device__ unsigned g_bargen = 0;

// ---------------- grid barrier (148 co-resident blocks) ----------------
__device__ __forceinline__ void gbar() {
    __syncthreads();
    if (threadIdx.x == 0) {
        volatile unsigned* vg = &g_bargen;
        unsigned gen = *vg;
        __threadfence();
        if (atomicAdd(&g_barcnt, 1u) == NBLK - 1) {
            g_barcnt = 0;
            __threadfence();
            *vg = gen + 1;
        } else {
            while (*vg == gen) { __nanosleep(32); }
        }
        __threadfence();
    }
    __syncthreads();
}

// ---------------- fast activations (rel err ~1e-6, fine vs 1e-3 gate) ----------------
__device__ __forceinline__ float sigf(float x) {
    return __fdividef(1.f, 1.f + __expf(-x));
}
__device__ __forceinline__ float tanhfast(float x) {
    return 1.f - __fdividef(2.f, __expf(2.f * x) + 1.f);
}

// ---------------- fused LSTM cell tile ----------------
// Tile: 32 b-rows x JW hidden-units. Each thread owns (j, NB b-rows) and computes
// all 4 gate pre-activations (i,f,g,o) via packed f32x2 FMA, then the gate update.
// g = bias + A @ WihP + h @ WhhP ; c' = sig(f)*c + sig(i)*tanh(g) ; h' = sig(o)*tanh(c')
template<int JW>
__device__ void lstm_tile(float* smem, int st, int b0, int j0,
                          const float* __restrict__ A, long aStr, long aOff, int Kin,
                          const float* __restrict__ hsrc, float* __restrict__ hdst,
                          float* __restrict__ cst, float* __restrict__ yout)
{
    constexpr int NB = (32 * JW) / NTHR;     // b-rows per thread: 4 (JW=32) or 2 (JW=16)
    float* s_src = smem;                     // [32][64]   staged activations
    float* s_w   = smem + 32 * 64;           // [64][JW*4] staged packed weights

    const int tid  = threadIdx.x;
    const int jj   = tid % JW;
    const int bsub = tid / JW;
    const int jgl  = j0 + jj;

    ull accL[NB], accH[NB];                  // packed (i,f) and (g,o) accumulators
    {
        const float* bb = &g_bias[st][jgl * 4];
        ull bL = *(const ull*)bb;
        ull bH = *(const ull*)(bb + 2);
#pragma unroll
        for (int i = 0; i < NB; i++) { accL[i] = bL; accH[i] = bH; }
    }

#pragma unroll 1
    for (int seg = 0; seg < 2; seg++) {
        const float* S  = seg ? hsrc : A;
        long str        = seg ? (long)Hn : aStr;
        long off        = seg ? 0L : aOff;
        const float* W  = seg ? &g_wpH[st][0][0] : &g_wpA[st][0][0];
        int K           = seg ? Hn : Kin;
        const int wcols = JW * 4;

        for (int k0 = 0; k0 < K; k0 += 64) {
            int kc = (K - k0 < 64) ? (K - k0) : 64;
            __syncthreads();
            for (int idx = tid; idx < 32 * kc; idx += NTHR) {
                int bl = idx / kc, kk = idx - bl * kc;
                s_src[bl * 64 + kk] = S[(long)(b0 + bl) * str + off + k0 + kk];
            }
            for (int idx = tid; idx < kc * wcols; idx += NTHR) {
                int kk = idx / wcols, c = idx - kk * wcols;
                s_w[kk * wcols + c] = W[(long)(k0 + kk) * G4n + j0 * 4 + c];
            }
            __syncthreads();
#pragma unroll 4
            for (int kk = 0; kk < kc; kk++) {
                const ull* wp = (const ull*)&s_w[kk * wcols + jj * 4];
                ull wL = wp[0], wH = wp[1];
#pragma unroll
                for (int i = 0; i < NB; i++) {
                    float a = s_src[(bsub * NB + i) * 64 + kk];
                    ull a2;
                    asm("mov.b64 %0,{%1,%1};" : "=l"(a2) : "f"(a));
                    asm("fma.rn.f32x2 %0,%1,%2,%0;" : "+l"(accL[i]) : "l"(a2), "l"(wL));
                    asm("fma.rn.f32x2 %0,%1,%2,%0;" : "+l"(accH[i]) : "l"(a2), "l"(wH));
                }
            }
        }
    }

    // gate update — this thread exclusively owns (b, jgl)
#pragma unroll
    for (int i = 0; i < NB; i++) {
        float gi, gf, gg, go;
        asm("mov.b64 {%0,%1},%2;" : "=f"(gi), "=f"(gf) : "l"(accL[i]));
        asm("mov.b64 {%0,%1},%2;" : "=f"(gg), "=f"(go) : "l"(accH[i]));
        int b = b0 + bsub * NB + i;
        long ci = (long)b * Hn + jgl;
        float cold = cst[ci];
        float cn = sigf(gf) * cold + sigf(gi) * tanhfast(gg);
        float hn = sigf(go) * tanhfast(cn);
        cst[ci]  = cn;
        hdst[ci] = hn;
        if (yout) yout[(long)b * (2 * Hn) + jgl] = hn;
    }
}

// ---------------- the persistent kernel ----------------
__global__ void __launch_bounds__(NTHR, 1) orbit_kernel(Params P)
{
    __shared__ float smem[32 * 64 + 64 * 128];   // 40 KB
    const int tid  = threadIdx.x;
    const int gtid = blockIdx.x * NTHR + tid;
    const int gstr = NBLK * NTHR;

    // ===== Phase 0: pack weights [4H x K] -> [K][j*4+gate], biases; zero enc states =====
    {
        const int KIN[6] = {INn, INn, 2 * Hn, 2 * Hn, OUTn, Hn};
#pragma unroll 1
        for (int s6 = 0; s6 < 6; s6++) {
            const float* whh = P.whh[s6];
            for (int e = gtid; e < Hn * G4n; e += gstr) {
                int k = e >> 9, col = e & 511;
                int j = col >> 2, g = col & 3;
                g_wpH[s6][k][col] = whh[(g * Hn + j) * Hn + k];
            }
            int kin = KIN[s6];
            const float* wih = P.wih[s6];
            for (int e = gtid; e < kin * G4n; e += gstr) {
                int k = e >> 9, col = e & 511;
                int j = col >> 2, g = col & 3;
                g_wpA[s6][k][col] = wih[(g * Hn + j) * kin + k];
            }
            const float* bi = P.bih[s6];
            const float* bh = P.bhh[s6];
            for (int e = gtid; e < G4n; e += gstr) {
                int j = e >> 2, g = e & 3;
                g_bias[s6][e] = bi[g * Hn + j] + bh[g * Hn + j];
            }
        }
        float* h0 = &g_h[0][0][0][0];
        float* c0 = &g_c[0][0][0];
        for (int e = gtid; e < 4 * Bn * Hn; e += gstr) { h0[e] = 0.f; c0[e] = 0.f; }
    }
    gbar();

    // ===== Phase 1/2: encoder layers 0 and 1 (fwd & bwd run concurrently per step) =====
#pragma unroll 1
    for (int layer = 0; layer < 2; layer++) {
#pragma unroll 1
        for (int s = 0; s < Tn; s++) {
            int cur = s & 1, nxt = cur ^ 1;
            int tl = blockIdx.x;
            if (tl < 128) {
                int dir = tl >> 6;
                int rem = tl & 63;
                int b0  = (rem >> 2) * 32;
                int j0  = (rem & 3) * 32;
                int st  = layer * 2 + dir;
                int t   = dir ? (Tn - 1 - s) : s;
                if (layer == 0) {
                    lstm_tile<32>(smem, st, b0, j0,
                        P.x, (long)Tn * INn, (long)t * INn, INn,
                        &g_h[cur][st][0][0], &g_h[nxt][st][0][0], &g_c[st][0][0],
                        g_y0 + (size_t)t * Bn * 2 * Hn + dir * Hn);
                } else {
                    lstm_tile<32>(smem, st, b0, j0,
                        g_y0 + (size_t)t * Bn * 2 * Hn, (long)(2 * Hn), 0L, 2 * Hn,
                        &g_h[cur][st][0][0], &g_h[nxt][st][0][0], &g_c[st][0][0],
                        nullptr);
                }
            }
            gbar();
        }
    }

    // ===== Phase 3: bridge (h_dec/c_dec) + start token =====
    {
        // cells: typ(2) x layer(2) x b(512) x j(128) = 2^18
        for (int idx = gtid; idx < (1 << 18); idx += gstr) {
            int j   = idx & (Hn - 1);
            int b   = (idx >> 7) & (Bn - 1);
            int l   = (idx >> 16) & 1;
            int typ = idx >> 17;
            const float* W    = typ ? P.brc_W : P.brh_W;
            const float* bias = typ ? P.brc_b : P.brh_b;
            const float* srcF = typ ? &g_c[2 * l][0][0] : &g_h[0][2 * l][0][0];
            const float* srcB = typ ? &g_c[2 * l + 1][0][0] : &g_h[0][2 * l + 1][0][0];
            const float* wr = &W[j * 2 * Hn];
            float acc = bias[j];
#pragma unroll 4
            for (int k = 0; k < Hn; k++) acc += srcF[b * Hn + k] * wr[k];
#pragma unroll 4
            for (int k = 0; k < Hn; k++) acc += srcB[b * Hn + k] * wr[Hn + k];
            if (typ) g_c[4 + l][b][j] = acc;
            else     g_h[0][4 + l][b][j] = acc;
        }
        for (int idx = gtid; idx < Bn * OUTn; idx += gstr)
            g_xin[idx] = P.start[idx % OUTn];
    }
    gbar();

    // ===== Phase 4: autoregressive decoder =====
#pragma unroll 1
    for (int s = 0; s < HORn; s++) {
        int cur = s & 1, nxt = cur ^ 1;
        int tl = blockIdx.x;
        int b0 = 0, j0 = 0;
        if (tl < 128) { b0 = (tl >> 3) * 32; j0 = (tl & 7) * 16; }

        // cell 0: input = previous prediction (K=3) + h (K=128)
        if (tl < 128)
            lstm_tile<16>(smem, 4, b0, j0, g_xin, (long)OUTn, 0L, OUTn,
                          &g_h[cur][4][0][0], &g_h[nxt][4][0][0], &g_c[4][0][0], nullptr);
        gbar();

        // cell 1: input = cell0's new h (K=128) + own h (K=128)
        if (tl < 128)
            lstm_tile<16>(smem, 5, b0, j0, &g_h[nxt][4][0][0], (long)Hn, 0L, Hn,
                          &g_h[cur][5][0][0], &g_h[nxt][5][0][0], &g_c[5][0][0], nullptr);
        gbar();

        // prediction head + autoregressive feedback
        if (tl < 6) {
            int idx = tl * NTHR + tid;          // 0..1535 = 512*3
            int b = idx / OUTn, o = idx - b * OUTn;
            const float* hp = &g_h[nxt][5][b][0];
            const float* wp = &P.out_W[o * Hn];
            float acc = P.out_b[o];
#pragma unroll 8
            for (int k = 0; k < Hn; k++) acc += hp[k] * wp[k];
            P.out[(size_t)b * HORn * OUTn + (size_t)s * OUTn + o] = acc;
            g_xin[b * OUTn + o] = acc;
        }
        gbar();
    }
}

// ---------------- launch ----------------
extern "C" void kernel_launch(void* const* d_in, const int* in_sizes, int n_in,
                              void* d_out, int out_size)
{
    (void)in_sizes; (void)n_in; (void)out_size;
    Params P;
    P.x = (const float*)d_in[0];
    const int base[6] = {1, 5, 9, 13, 21, 25};   // e0f,e0b,e1f,e1b,d0,d1
    for (int i = 0; i < 6; i++) {
        P.wih[i] = (const float*)d_in[base[i] + 0];
        P.whh[i] = (const float*)d_in[base[i] + 1];
        P.bih[i] = (const float*)d_in[base[i] + 2];
        P.bhh[i] = (const float*)d_in[base[i] + 3];
    }
    P.brh_W = (const float*)d_in[17];
    P.brh_b = (const float*)d_in[18];
    P.brc_W = (const float*)d_in[19];
    P.brc_b = (const float*)d_in[20];
    P.out_W = (const float*)d_in[29];
    P.out_b = (const float*)d_in[30];
    P.start = (const float*)d_in[31];
    P.out   = (float*)d_out;

    orbit_kernel<<<NBLK, NTHR>>>(P);
}

// round 5
// speedup vs baseline: 1.1960x; 1.1936x over previous
#include <cuda_runtime.h>

#define Tn   720
#define Bn   512
#define INn  6
#define Hn   128
#define OUTn 3
#define HORn 360
#define NBLK 148
#define NTHR 512

typedef unsigned long long ull;

struct Params {
    const float* x;
    const float* wih[6];   // e0f,e0b,e1f,e1b,d0,d1
    const float* whh[6];
    const float* bih[6];
    const float* bhh[6];
    const float* brh_W; const float* brh_b;
    const float* brc_W; const float* brc_b;
    const float* out_W; const float* out_b;
    const float* start;
    float* out;
};

// ---------------- scratch (device globals; no allocation allowed) ----------------
__device__ float g_y0[(size_t)Tn * Bn * 2 * Hn];      // encoder layer0 outputs [t][b][256]
__device__ float g_h[2][6][Bn][Hn];                   // double-buffered hidden state
__device__ float g_c[6][Bn][Hn];                      // cell state (in-place)
__device__ float g_xin[Bn * OUTn];                    // decoder autoregressive input
__device__ unsigned g_barcnt = 0;
__device__ unsigned g_bargen = 0;
__device__ unsigned g_gcnt[16 * 32];                  // 16 group counters, 128B apart
__device__ unsigned g_ggen[16 * 32];

// ---------------- shared-memory layout (dynamic, ~114KB) ----------------
#define SW_ROWS   387                 // max K rows: decoder (3+128)+(128+128)=387; enc L1 = 384
#define SW_FLOATS (SW_ROWS * 64)      // [row][jloc*4+gate], 16 j per block
#define SA_OFF    SW_FLOATS
#define SA_FLOATS (64 * 65)           // act staging [kk][b], padded stride 65
#define SB_OFF    (SA_OFF + SA_FLOATS)
#define SMEM_FLOATS (SB_OFF + 128)    // 2 bias slots x 64
#define SMEM_BYTES  (SMEM_FLOATS * 4)

// ---------------- full grid barrier (phase boundaries only) ----------------
__device__ __forceinline__ void gbar() {
    __syncthreads();
    if (threadIdx.x == 0) {
        volatile unsigned* vg = &g_bargen;
        unsigned gen = *vg;
        __threadfence();
        if (atomicAdd(&g_barcnt, 1u) == NBLK - 1) {
            g_barcnt = 0;
            __threadfence();
            *vg = gen + 1;
        } else {
            while (*vg == gen) { __nanosleep(32); }
        }
        __threadfence();
    }
    __syncthreads();
}

// ---------------- 8-block group barrier (per recurrent step) ----------------
__device__ __forceinline__ void groupbar(int g) {
    __syncthreads();
    if (threadIdx.x == 0) {
        volatile unsigned* vg = &g_ggen[g * 32];
        unsigned gen = *vg;
        __threadfence();                       // release (+ CCTL.IVALL on sm_103a)
        if (atomicAdd(&g_gcnt[g * 32], 1u) == 7u) {
            g_gcnt[g * 32] = 0;
            __threadfence();
            *vg = gen + 1;
        } else {
            while (*vg == gen) { __nanosleep(20); }
        }
        __threadfence();                       // acquire: invalidate L1
    }
    __syncthreads();
}

// ---------------- fast activations ----------------
__device__ __forceinline__ float sigf(float x) {
    return __fdividef(1.f, 1.f + __expf(-x));
}
__device__ __forceinline__ float tanhfast(float x) {
    return 1.f - __fdividef(2.f, __expf(2.f * x) + 1.f);
}

// ---------------- per-phase weight packing into smem ----------------
// s_w rows [rowBase .. rowBase+Kin+H): first Kin rows = Wih, next H rows = Whh,
// packed as [row][jloc*4+gate] for this block's 16 j's.
__device__ void pack_cell(float* __restrict__ s_w, float* __restrict__ s_bias,
                          const float* __restrict__ wih, const float* __restrict__ whh,
                          const float* __restrict__ bih, const float* __restrict__ bhh,
                          int Kin, int j0, int rowBase, int biasSlot)
{
    int total = (Kin + Hn) * 64;
    for (int e = threadIdx.x; e < total; e += NTHR) {
        int row = e >> 6, c = e & 63;
        int j = j0 + (c >> 2), g = c & 3;
        float v = (row < Kin) ? wih[(g * Hn + j) * Kin + row]
                              : whh[(g * Hn + j) * Hn + (row - Kin)];
        s_w[(size_t)(rowBase + row) * 64 + c] = v;
    }
    for (int e = threadIdx.x; e < 64; e += NTHR) {
        int j = j0 + (e >> 2), g = e & 3;
        s_bias[biasSlot * 64 + e] = bih[g * Hn + j] + bhh[g * Hn + j];
    }
}

// ---------------- fused LSTM cell tile ----------------
// Tile: BT b-rows x 16 j's with 512 threads. lane = b (coalesced/broadcast-friendly),
// warp = j (weight loads broadcast). Each thread owns NB (b,j) pairs & all 4 gates.
template<int BT, int NB>
__device__ void cell_tile(float* __restrict__ s_w, float* __restrict__ s_a,
                          const float* __restrict__ s_bias,
                          int b0, int j0g,
                          const float* __restrict__ A, long aStr, long aOff, int Kin, int rowBase,
                          const float* __restrict__ hsrc, float* __restrict__ hdst,
                          float* __restrict__ cst, float* __restrict__ yout, int yStr)
{
    const int tid  = threadIdx.x;
    const int lane = tid & 31;
    const int jloc = tid >> 5;            // 0..15
    const int jgl  = j0g + jloc;

    ull accL[NB], accH[NB];               // packed (i,f) and (g,o)
    {
        ull bL = *(const ull*)&s_bias[jloc * 4];
        ull bH = *(const ull*)&s_bias[jloc * 4 + 2];
#pragma unroll
        for (int i = 0; i < NB; i++) { accL[i] = bL; accH[i] = bH; }
    }

#pragma unroll 1
    for (int seg = 0; seg < 2; seg++) {
        const float* S = seg ? hsrc : A;
        long str       = seg ? (long)Hn : aStr;
        long off       = seg ? 0L : aOff;
        int  K         = seg ? Hn : Kin;
        int  wr0       = rowBase + (seg ? Kin : 0);

        for (int k0 = 0; k0 < K; k0 += 64) {
            int kc = (K - k0 < 64) ? (K - k0) : 64;
            __syncthreads();
            // stage activations: [kk][b], stride BT+1 (conflict-free both ways)
            for (int e = tid; e < BT * kc; e += NTHR) {
                int b = e / kc, kk = e - b * kc;
                s_a[kk * (BT + 1) + b] = S[(long)(b0 + b) * str + off + k0 + kk];
            }
            __syncthreads();

            const float* wp = s_w + (size_t)(wr0 + k0) * 64 + jloc * 4;
            const float* ap = s_a + lane;
#pragma unroll 4
            for (int kk = 0; kk < kc; kk++) {
                ulonglong2 w = *(const ulonglong2*)wp;   // LDS.128, warp-broadcast
                wp += 64;
#pragma unroll
                for (int i = 0; i < NB; i++) {
                    float a = ap[32 * i];                // coalesced LDS.32
                    ull a2;
                    asm("mov.b64 %0,{%1,%1};" : "=l"(a2) : "f"(a));
                    asm("fma.rn.f32x2 %0,%1,%2,%0;" : "+l"(accL[i]) : "l"(a2), "l"(w.x));
                    asm("fma.rn.f32x2 %0,%1,%2,%0;" : "+l"(accH[i]) : "l"(a2), "l"(w.y));
                }
                ap += BT + 1;
            }
        }
    }

    // gate update — thread exclusively owns (b, jgl)
#pragma unroll
    for (int i = 0; i < NB; i++) {
        float gi, gf, gg, go;
        asm("mov.b64 {%0,%1},%2;" : "=f"(gi), "=f"(gf) : "l"(accL[i]));
        asm("mov.b64 {%0,%1},%2;" : "=f"(gg), "=f"(go) : "l"(accH[i]));
        int b = b0 + lane + 32 * i;
        long ci = (long)b * Hn + jgl;
        float cold = cst[ci];
        float cn = sigf(gf) * cold + sigf(gi) * tanhfast(gg);
        float hn = sigf(go) * tanhfast(cn);
        cst[ci]  = cn;
        hdst[ci] = hn;
        if (yout) yout[(long)b * yStr + jgl] = hn;
    }
}

// ---------------- the persistent kernel ----------------
__global__ void __launch_bounds__(NTHR, 1) orbit_kernel(Params P)
{
    extern __shared__ float smem[];
    float* s_w    = smem;
    float* s_a    = smem + SA_OFF;
    float* s_bias = smem + SB_OFF;

    const int tid  = threadIdx.x;
    const int bid  = blockIdx.x;
    const int gtid = bid * NTHR + tid;
    const int gstr = NBLK * NTHR;

    // ===== Phase 0: zero encoder states =====
    {
        float* h0 = &g_h[0][0][0][0];
        float* c0 = &g_c[0][0][0];
        for (int e = gtid; e < 4 * Bn * Hn; e += gstr) { h0[e] = 0.f; c0[e] = 0.f; }
    }
    gbar();

    // ===== Encoder: layers 0 and 1, fwd & bwd concurrent =====
    // bid<128: dir = bid>>6, b-tile = (bid>>3)&7 (64 b's), j-tile = bid&7 (16 j's)
    const int dir = bid >> 6;
    const int btE = (bid >> 3) & 7;
    const int jbE = bid & 7;
    const int b0E = btE * 64;
    const int j0E = jbE * 16;

#pragma unroll 1
    for (int layer = 0; layer < 2; layer++) {
        int st = layer * 2 + dir;
        if (bid < 128) {
            int kin = layer ? 2 * Hn : INn;
            pack_cell(s_w, s_bias, P.wih[st], P.whh[st], P.bih[st], P.bhh[st],
                      kin, j0E, 0, 0);
        }
        __syncthreads();
#pragma unroll 1
        for (int s = 0; s < Tn; s++) {
            int cur = s & 1, nxt = cur ^ 1;
            if (bid < 128) {
                int t = dir ? (Tn - 1 - s) : s;
                if (layer == 0) {
                    cell_tile<64, 2>(s_w, s_a, s_bias, b0E, j0E,
                        P.x, (long)Tn * INn, (long)t * INn, INn, 0,
                        &g_h[cur][st][0][0], &g_h[nxt][st][0][0], &g_c[st][0][0],
                        g_y0 + (size_t)t * Bn * 2 * Hn + dir * Hn, 2 * Hn);
                } else {
                    cell_tile<64, 2>(s_w, s_a, s_bias, b0E, j0E,
                        g_y0 + (size_t)t * Bn * 2 * Hn, (long)(2 * Hn), 0L, 2 * Hn, 0,
                        &g_h[cur][st][0][0], &g_h[nxt][st][0][0], &g_c[st][0][0],
                        nullptr, 0);
                }
                groupbar(bid >> 3);   // only the 8 j-blocks of (dir,b-tile) couple
            }
        }
        gbar();                       // layer boundary: y0 / final states global
    }

    // ===== Bridge: h_dec/c_dec + start token (final enc states in buffer 0) =====
    {
        for (int idx = gtid; idx < (1 << 18); idx += gstr) {
            int j   = idx & (Hn - 1);
            int b   = (idx >> 7) & (Bn - 1);
            int l   = (idx >> 16) & 1;
            int typ = idx >> 17;
            const float* W    = typ ? P.brc_W : P.brh_W;
            const float* bias = typ ? P.brc_b : P.brh_b;
            const float* srcF = typ ? &g_c[2 * l][0][0] : &g_h[0][2 * l][0][0];
            const float* srcB = typ ? &g_c[2 * l + 1][0][0] : &g_h[0][2 * l + 1][0][0];
            const float* wr = &W[j * 2 * Hn];
            float acc = bias[j];
#pragma unroll 4
            for (int k = 0; k < Hn; k++) acc += srcF[b * Hn + k] * wr[k];
#pragma unroll 4
            for (int k = 0; k < Hn; k++) acc += srcB[b * Hn + k] * wr[Hn + k];
            if (typ) g_c[4 + l][b][j] = acc;
            else     g_h[0][4 + l][b][j] = acc;
        }
        for (int idx = gtid; idx < Bn * OUTn; idx += gstr)
            g_xin[idx] = P.start[idx % OUTn];
    }
    gbar();

    // ===== Decoder: 32-b x 16-j tiles; group = 8 j-blocks per b-tile =====
    const int btD = bid >> 3;          // 0..15
    const int jbD = bid & 7;
    const int b0D = btD * 32;
    const int j0D = jbD * 16;

    if (bid < 128) {
        pack_cell(s_w, s_bias, P.wih[4], P.whh[4], P.bih[4], P.bhh[4], OUTn, j0D, 0,   0);
        pack_cell(s_w, s_bias, P.wih[5], P.whh[5], P.bih[5], P.bhh[5], Hn,   j0D, 131, 1);
    }
    __syncthreads();

#pragma unroll 1
    for (int s = 0; s < HORn; s++) {
        int cur = s & 1, nxt = cur ^ 1;
        if (bid < 128) {
            // cell 0: input = previous prediction (K=3) + own h (K=128)
            cell_tile<32, 1>(s_w, s_a, s_bias, b0D, j0D,
                g_xin, (long)OUTn, 0L, OUTn, 0,
                &g_h[cur][4][0][0], &g_h[nxt][4][0][0], &g_c[4][0][0], nullptr, 0);
            groupbar(btD);

            // cell 1: input = cell0's new h (K=128) + own h (K=128)
            cell_tile<32, 1>(s_w, s_a, s_bias + 64, b0D, j0D,
                &g_h[nxt][4][0][0], (long)Hn, 0L, Hn, 131,
                &g_h[cur][5][0][0], &g_h[nxt][5][0][0], &g_c[5][0][0], nullptr, 0);
            groupbar(btD);

            // prediction head: group's 96 (b,o) dots spread 12 per block, warp-reduced
            {
                int w = tid >> 5, lane = tid & 31;
                if (w < 12) {
                    int oi = jbD * 12 + w;              // 0..95 within group
                    int b  = b0D + oi / 3;
                    int o  = oi - (oi / 3) * 3;
                    const float4* hp = (const float4*)&g_h[nxt][5][b][0];
                    const float4* wp = (const float4*)&P.out_W[o * Hn];
                    float4 hv = hp[lane];
                    float4 wv = wp[lane];
                    float v = hv.x * wv.x + hv.y * wv.y + hv.z * wv.z + hv.w * wv.w;
#pragma unroll
                    for (int d = 16; d; d >>= 1) v += __shfl_down_sync(0xffffffffu, v, d);
                    if (lane == 0) {
                        v += P.out_b[o];
                        P.out[(size_t)b * HORn * OUTn + (size_t)s * OUTn + o] = v;
                        g_xin[b * OUTn + o] = v;
                    }
                }
            }
            groupbar(btD);
        }
    }
}

// ---------------- launch ----------------
extern "C" void kernel_launch(void* const* d_in, const int* in_sizes, int n_in,
                              void* d_out, int out_size)
{
    (void)in_sizes; (void)n_in; (void)out_size;
    Params P;
    P.x = (const float*)d_in[0];
    const int base[6] = {1, 5, 9, 13, 21, 25};   // e0f,e0b,e1f,e1b,d0,d1
    for (int i = 0; i < 6; i++) {
        P.wih[i] = (const float*)d_in[base[i] + 0];
        P.whh[i] = (const float*)d_in[base[i] + 1];
        P.bih[i] = (const float*)d_in[base[i] + 2];
        P.bhh[i] = (const float*)d_in[base[i] + 3];
    }
    P.brh_W = (const float*)d_in[17];
    P.brh_b = (const float*)d_in[18];
    P.brc_W = (const float*)d_in[19];
    P.brc_b = (const float*)d_in[20];
    P.out_W = (const float*)d_in[29];
    P.out_b = (const float*)d_in[30];
    P.start = (const float*)d_in[31];
    P.out   = (float*)d_out;

    cudaFuncSetAttribute(orbit_kernel, cudaFuncAttributeMaxDynamicSharedMemorySize,
                         SMEM_BYTES);
    orbit_kernel<<<NBLK, NTHR, SMEM_BYTES>>>(P);
}

// round 8
// speedup vs baseline: 1.3681x; 1.1439x over previous
#include <cuda_runtime.h>

#define Tn   720
#define Bn   512
#define INn  6
#define Hn   128
#define OUTn 3
#define HORn 360
#define NBLK 148
#define NTHR 512
#define CHK  128
#define STRD 132   // [b][kk] staging stride: 33*16B -> conflict-free LDS.128

typedef unsigned long long ull;

struct Params {
    const float* x;
    const float* wih[6];   // e0f,e0b,e1f,e1b,d0,d1
    const float* whh[6];
    const float* bih[6];
    const float* bhh[6];
    const float* brh_W; const float* brh_b;
    const float* brc_W; const float* brc_b;
    const float* out_W; const float* out_b;
    const float* start;
    float* out;
};

// ---------------- scratch (device globals; no allocation allowed) ----------------
__device__ float g_y0[(size_t)Tn * Bn * 2 * Hn];      // encoder layer0 outputs [t][b][256]
__device__ float g_h[2][6][Bn][Hn];                   // double-buffered hidden state
__device__ float g_c[6][Bn][Hn];                      // cell state (in-place)
__device__ float g_xin[Bn * OUTn];                    // decoder autoregressive input
__device__ unsigned g_barcnt = 0;
__device__ unsigned g_bargen = 0;
__device__ unsigned g_gcnt[16 * 32];                  // 16 group counters, 128B apart
__device__ unsigned g_ggen[16 * 32];

// ---------------- shared-memory layout (dynamic, ~130KB) ----------------
#define SW_FLOATS (387 * 64)            // weights [row][jloc*4+gate], 16 j per block
#define SA_FLOATS (64 * STRD)           // act staging [b][kk], 64 b x 128 kk (+pad)
#define SB_OFF    (SW_FLOATS + SA_FLOATS)
#define SMEM_BYTES ((SB_OFF + 128) * 4)

// ---------------- full grid barrier (phase boundaries only) ----------------
__device__ __forceinline__ void gbar() {
    __syncthreads();
    if (threadIdx.x == 0) {
        volatile unsigned* vg = &g_bargen;
        unsigned gen = *vg;
        __threadfence();
        if (atomicAdd(&g_barcnt, 1u) == NBLK - 1) {
            g_barcnt = 0;
            __threadfence();
            *vg = gen + 1;
        } else {
            while (*vg == gen) { __nanosleep(32); }
        }
        __threadfence();
    }
    __syncthreads();
}

// ---------------- 8-block group barrier (per recurrent step) ----------------
__device__ __forceinline__ void groupbar(int g) {
    __syncthreads();
    if (threadIdx.x == 0) {
        volatile unsigned* vg = &g_ggen[g * 32];
        unsigned gen = *vg;
        __threadfence();                       // release
        if (atomicAdd(&g_gcnt[g * 32], 1u) == 7u) {
            g_gcnt[g * 32] = 0;
            __threadfence();
            *vg = gen + 1;
        } else {
            while (*vg == gen) { __nanosleep(20); }
        }
        __threadfence();                       // acquire: invalidate L1
    }
    __syncthreads();
}

// ---------------- fast activations ----------------
__device__ __forceinline__ float sigf(float x) {
    return __fdividef(1.f, 1.f + __expf(-x));
}
__device__ __forceinline__ float tanhfast(float x) {
    return 1.f - __fdividef(2.f, __expf(2.f * x) + 1.f);
}

// ---------------- per-phase weight packing into smem ----------------
// rows [rowBase .. rowBase+Kin+H): first Kin rows = Wih, next H rows = Whh,
// packed [row][jloc*4+gate] for this block's 16 j's.
__device__ void pack_cell(float* __restrict__ s_w, float* __restrict__ s_bias,
                          const float* __restrict__ wih, const float* __restrict__ whh,
                          const float* __restrict__ bih, const float* __restrict__ bhh,
                          int Kin, int j0, int rowBase, int biasSlot)
{
    int total = (Kin + Hn) * 64;
    for (int e = threadIdx.x; e < total; e += NTHR) {
        int row = e >> 6, c = e & 63;
        int j = j0 + (c >> 2), g = c & 3;
        float v = (row < Kin) ? wih[(g * Hn + j) * Kin + row]
                              : whh[(g * Hn + j) * Hn + (row - Kin)];
        s_w[(size_t)(rowBase + row) * 64 + c] = v;
    }
    for (int e = threadIdx.x; e < 64; e += NTHR) {
        int j = j0 + (e >> 2), g = e & 3;
        s_bias[biasSlot * 64 + e] = bih[g * Hn + j] + bhh[g * Hn + j];
    }
}

// ---------------- fused LSTM cell tile ----------------
// Tile: BT b-rows x 16 j's with 512 threads. lane = b, warp = j (weight loads
// broadcast). Each thread owns NB (b,j) pairs & all 4 gates. Activations staged
// [b][kk] so the main path reads 4 k's per float4 LDS.128.
template<int BT, int NB>
__device__ void cell_tile(float* __restrict__ s_w, float* __restrict__ s_a,
                          const float* __restrict__ s_bias,
                          int b0, int j0g,
                          const float* __restrict__ A, long aStr, long aOff, int Kin, int rowBase,
                          const float* __restrict__ hsrc, float* __restrict__ hdst,
                          float* __restrict__ cst, float* __restrict__ yout, int yStr)
{
    const int tid  = threadIdx.x;
    const int lane = tid & 31;
    const int jloc = tid >> 5;            // 0..15
    const int jgl  = j0g + jloc;

    ull accL[NB], accH[NB];               // packed (i,f) and (g,o)
    {
        ull bL = *(const ull*)&s_bias[jloc * 4];
        ull bH = *(const ull*)&s_bias[jloc * 4 + 2];
#pragma unroll
        for (int i = 0; i < NB; i++) { accL[i] = bL; accH[i] = bH; }
    }

#pragma unroll 1
    for (int seg = 0; seg < 2; seg++) {
        const float* S = seg ? hsrc : A;
        long str       = seg ? (long)Hn : aStr;
        long off       = seg ? 0L : aOff;
        int  K         = seg ? Hn : Kin;
        int  wr0       = rowBase + (seg ? Kin : 0);

        for (int k0 = 0; k0 < K; k0 += CHK) {
            int kc = (K - k0 < CHK) ? (K - k0) : CHK;
            __syncthreads();
            // stage activations: [b][kk] stride 132
            for (int idx = tid; idx < BT * kc; idx += NTHR) {
                int b, kk;
                if (kc == CHK) { b = idx >> 7; kk = idx & 127; }
                else           { b = idx / kc; kk = idx - b * kc; }
                s_a[b * STRD + kk] = S[(long)(b0 + b) * str + off + k0 + kk];
            }
            __syncthreads();

            const float* wp = s_w + (size_t)(wr0 + k0) * 64 + jloc * 4;
            if (kc == CHK) {
                // quad path: 4 k's per LDS.128 activation load
#pragma unroll 2
                for (int kq = 0; kq < CHK; kq += 4) {
                    float4 av[NB];
#pragma unroll
                    for (int i = 0; i < NB; i++)
                        av[i] = *(const float4*)&s_a[(lane + 32 * i) * STRD + kq];
#pragma unroll
                    for (int t = 0; t < 4; t++) {
                        ulonglong2 w = *(const ulonglong2*)(wp + (size_t)(kq + t) * 64);
#pragma unroll
                        for (int i = 0; i < NB; i++) {
                            float a = (t == 0) ? av[i].x : (t == 1) ? av[i].y
                                    : (t == 2) ? av[i].z : av[i].w;
                            ull a2; asm("mov.b64 %0,{%1,%1};" : "=l"(a2) : "f"(a));
                            asm("fma.rn.f32x2 %0,%1,%2,%0;" : "+l"(accL[i]) : "l"(a2), "l"(w.x));
                            asm("fma.rn.f32x2 %0,%1,%2,%0;" : "+l"(accH[i]) : "l"(a2), "l"(w.y));
                        }
                    }
                }
            } else {
                // scalar tail (K = 6 or 3)
                for (int kk = 0; kk < kc; kk++) {
                    ulonglong2 w = *(const ulonglong2*)(wp + (size_t)kk * 64);
#pragma unroll
                    for (int i = 0; i < NB; i++) {
                        float a = s_a[(lane + 32 * i) * STRD + kk];
                        ull a2; asm("mov.b64 %0,{%1,%1};" : "=l"(a2) : "f"(a));
                        asm("fma.rn.f32x2 %0,%1,%2,%0;" : "+l"(accL[i]) : "l"(a2), "l"(w.x));
                        asm("fma.rn.f32x2 %0,%1,%2,%0;" : "+l"(accH[i]) : "l"(a2), "l"(w.y));
                    }
                }
            }
        }
    }

    // gate update — thread exclusively owns (b, jgl)
#pragma unroll
    for (int i = 0; i < NB; i++) {
        float gi, gf, gg, go;
        asm("mov.b64 {%0,%1},%2;" : "=f"(gi), "=f"(gf) : "l"(accL[i]));
        asm("mov.b64 {%0,%1},%2;" : "=f"(gg), "=f"(go) : "l"(accH[i]));
        int b = b0 + lane + 32 * i;
        long ci = (long)b * Hn + jgl;
        float cold = cst[ci];
        float cn = sigf(gf) * cold + sigf(gi) * tanhfast(gg);
        float hn = sigf(go) * tanhfast(cn);
        cst[ci]  = cn;
        hdst[ci] = hn;
        if (yout) yout[(long)b * yStr + jgl] = hn;
    }
}

// ---------------- the persistent kernel ----------------
__global__ void __launch_bounds__(NTHR, 1) orbit_kernel(Params P)
{
    extern __shared__ float smem[];
    float* s_w    = smem;
    float* s_a    = smem + SW_FLOATS;
    float* s_bias = smem + SB_OFF;

    const int tid  = threadIdx.x;
    const int bid  = blockIdx.x;
    const int gtid = bid * NTHR + tid;
    const int gstr = NBLK * NTHR;

    // ===== Phase 0: zero encoder states =====
    {
        float* h0 = &g_h[0][0][0][0];
        float* c0 = &g_c[0][0][0];
        for (int e = gtid; e < 4 * Bn * Hn; e += gstr) { h0[e] = 0.f; c0[e] = 0.f; }
    }
    gbar();

    // ===== Encoder: group of 8 blocks covers (dir, 64-b tile); block owns 16 j =====
    const int dir = bid >> 6;
    const int btE = (bid >> 3) & 7;
    const int jbE = bid & 7;
    const int b0E = btE * 64;
    const int j0E = jbE * 16;

#pragma unroll 1
    for (int layer = 0; layer < 2; layer++) {
        int st  = layer * 2 + dir;
        if (bid < 128) {
            int kin = layer ? 2 * Hn : INn;
            pack_cell(s_w, s_bias, P.wih[st], P.whh[st], P.bih[st], P.bhh[st], kin, j0E, 0, 0);
        }
        __syncthreads();
#pragma unroll 1
        for (int s = 0; s < Tn; s++) {
            int cur = s & 1, nxt = cur ^ 1;
            if (bid < 128) {
                int t = dir ? (Tn - 1 - s) : s;
                if (layer == 0) {
                    cell_tile<64, 2>(s_w, s_a, s_bias, b0E, j0E,
                        P.x, (long)Tn * INn, (long)t * INn, INn, 0,
                        &g_h[cur][st][0][0], &g_h[nxt][st][0][0], &g_c[st][0][0],
                        g_y0 + (size_t)t * Bn * 2 * Hn + dir * Hn, 2 * Hn);
                } else {
                    cell_tile<64, 2>(s_w, s_a, s_bias, b0E, j0E,
                        g_y0 + (size_t)t * Bn * 2 * Hn, (long)(2 * Hn), 0L, 2 * Hn, 0,
                        &g_h[cur][st][0][0], &g_h[nxt][st][0][0], &g_c[st][0][0],
                        nullptr, 0);
                }
                groupbar(bid >> 3);   // only the 8 j-blocks of (dir,b-tile) couple
            }
        }
        gbar();                       // layer boundary: y0 / final states global
    }

    // ===== Bridge: h_dec/c_dec + start token (final enc states in buffer 0) =====
    {
        for (int idx = gtid; idx < (1 << 18); idx += gstr) {
            int j   = idx & (Hn - 1);
            int b   = (idx >> 7) & (Bn - 1);
            int l   = (idx >> 16) & 1;
            int typ = idx >> 17;
            const float* W    = typ ? P.brc_W : P.brh_W;
            const float* bias = typ ? P.brc_b : P.brh_b;
            const float* srcF = typ ? &g_c[2 * l][0][0] : &g_h[0][2 * l][0][0];
            const float* srcB = typ ? &g_c[2 * l + 1][0][0] : &g_h[0][2 * l + 1][0][0];
            const float* wr = &W[j * 2 * Hn];
            float acc = bias[j];
#pragma unroll 4
            for (int k = 0; k < Hn; k++) acc += srcF[b * Hn + k] * wr[k];
#pragma unroll 4
            for (int k = 0; k < Hn; k++) acc += srcB[b * Hn + k] * wr[Hn + k];
            if (typ) g_c[4 + l][b][j] = acc;
            else     g_h[0][4 + l][b][j] = acc;
        }
        for (int idx = gtid; idx < Bn * OUTn; idx += gstr)
            g_xin[idx] = P.start[idx % OUTn];
    }
    gbar();

    // ===== Decoder: group of 8 blocks covers 32-b tile; block owns 16 j =====
    const int btD = bid >> 3;          // 0..15
    const int jbD = bid & 7;
    const int b0D = btD * 32;
    const int j0D = jbD * 16;

    if (bid < 128) {
        pack_cell(s_w, s_bias, P.wih[4], P.whh[4], P.bih[4], P.bhh[4], OUTn, j0D, 0,   0);
        pack_cell(s_w, s_bias, P.wih[5], P.whh[5], P.bih[5], P.bhh[5], Hn,   j0D, 131, 1);
    }
    __syncthreads();

#pragma unroll 1
    for (int s = 0; s < HORn; s++) {
        int cur = s & 1, nxt = cur ^ 1;
        if (bid < 128) {
            // cell 0: input = previous prediction (K=3) + own h (K=128)
            cell_tile<32, 1>(s_w, s_a, s_bias, b0D, j0D,
                g_xin, (long)OUTn, 0L, OUTn, 0,
                &g_h[cur][4][0][0], &g_h[nxt][4][0][0], &g_c[4][0][0], nullptr, 0);
            groupbar(btD);

            // cell 1: input = cell0's new h (K=128) + own h (K=128)
            cell_tile<32, 1>(s_w, s_a, s_bias + 64, b0D, j0D,
                &g_h[nxt][4][0][0], (long)Hn, 0L, Hn, 131,
                &g_h[cur][5][0][0], &g_h[nxt][5][0][0], &g_c[5][0][0], nullptr, 0);
            groupbar(btD);

            // prediction head: group's 96 (b,o) dots spread 12 warps per block
            {
                int w = tid >> 5, lane = tid & 31;
                if (w < 12) {
                    int oi = jbD * 12 + w;              // 0..95 within group
                    int b  = b0D + oi / 3;
                    int o  = oi - (oi / 3) * 3;
                    float4 hv = ((const float4*)&g_h[nxt][5][b][0])[lane];
                    float4 wv = ((const float4*)&P.out_W[o * Hn])[lane];
                    float v = hv.x * wv.x + hv.y * wv.y + hv.z * wv.z + hv.w * wv.w;
#pragma unroll
                    for (int d = 16; d; d >>= 1) v += __shfl_down_sync(0xffffffffu, v, d);
                    if (lane == 0) {
                        v += P.out_b[o];
                        P.out[(size_t)b * HORn * OUTn + (size_t)s * OUTn + o] = v;
                        g_xin[b * OUTn + o] = v;
                    }
                }
            }
            groupbar(btD);
        }
    }
}

// ---------------- launch ----------------
extern "C" void kernel_launch(void* const* d_in, const int* in_sizes, int n_in,
                              void* d_out, int out_size)
{
    (void)in_sizes; (void)n_in; (void)out_size;
    Params P;
    P.x = (const float*)d_in[0];
    const int base[6] = {1, 5, 9, 13, 21, 25};   // e0f,e0b,e1f,e1b,d0,d1
    for (int i = 0; i < 6; i++) {
        P.wih[i] = (const float*)d_in[base[i] + 0];
        P.whh[i] = (const float*)d_in[base[i] + 1];
        P.bih[i] = (const float*)d_in[base[i] + 2];
        P.bhh[i] = (const float*)d_in[base[i] + 3];
    }
    P.brh_W = (const float*)d_in[17];
    P.brh_b = (const float*)d_in[18];
    P.brc_W = (const float*)d_in[19];
    P.brc_b = (const float*)d_in[20];
    P.out_W = (const float*)d_in[29];
    P.out_b = (const float*)d_in[30];
    P.start = (const float*)d_in[31];
    P.out   = (float*)d_out;

    cudaFuncSetAttribute(orbit_kernel, cudaFuncAttributeMaxDynamicSharedMemorySize,
                         SMEM_BYTES);
    orbit_kernel<<<NBLK, NTHR, SMEM_BYTES>>>(P);
}

// round 9
// speedup vs baseline: 1.5304x; 1.1186x over previous
#include <cuda_runtime.h>

#define Tn   720
#define Bn   512
#define INn  6
#define Hn   128
#define OUTn 3
#define HORn 360
#define NBLK 148
#define NTHR 512
#define CHK  128
#define STRD 132   // [b][kk] staging stride: 33*16B -> conflict-free LDS.128

typedef unsigned long long ull;

struct Params {
    const float* x;
    const float* wih[6];   // e0f,e0b,e1f,e1b,d0,d1
    const float* whh[6];
    const float* bih[6];
    const float* bhh[6];
    const float* brh_W; const float* brh_b;
    const float* brc_W; const float* brc_b;
    const float* out_W; const float* out_b;
    const float* start;
    float* out;
};

// ---------------- scratch (device globals; no allocation allowed) ----------------
__device__ float g_y0[(size_t)Tn * Bn * 2 * Hn];      // encoder layer0 outputs [t][b][256]
__device__ float g_h[2][6][Bn][Hn];                   // double-buffered hidden state
__device__ float g_c[6][Bn][Hn];                      // cell state (in-place)
__device__ float g_xin[Bn * OUTn];                    // decoder autoregressive input
__device__ unsigned g_barcnt = 0;
__device__ unsigned g_bargen = 0;
__device__ unsigned g_gcnt[16 * 32];                  // 16 group counters, 128B apart
__device__ unsigned g_ggen[16 * 32];

// ---------------- shared-memory layout (dynamic, ~167KB) ----------------
#define SW_FLOATS (387 * 64)            // weights [row][jloc*4+gate], 16 j per block
#define SA_FLOATS (64 * STRD)           // one staging buffer: 64 b x 128 kk (+pad)
#define SB_OFF    (SW_FLOATS + 2 * SA_FLOATS)
#define SMEM_BYTES ((SB_OFF + 128) * 4)

// ---------------- cp.async helpers ----------------
__device__ __forceinline__ void cp16(unsigned saddr, const float* g) {
    asm volatile("cp.async.ca.shared.global [%0], [%1], 16;" :: "r"(saddr), "l"(g));
}
#define CP_COMMIT() asm volatile("cp.async.commit_group;" ::: "memory")
#define CP_WAIT0()  asm volatile("cp.async.wait_group 0;" ::: "memory")

// ---------------- full grid barrier (phase boundaries only) ----------------
__device__ __forceinline__ void gbar() {
    __syncthreads();
    if (threadIdx.x == 0) {
        volatile unsigned* vg = &g_bargen;
        unsigned gen = *vg;
        __threadfence();
        if (atomicAdd(&g_barcnt, 1u) == NBLK - 1) {
            g_barcnt = 0;
            __threadfence();
            *vg = gen + 1;
        } else {
            while (*vg == gen) { __nanosleep(32); }
        }
        __threadfence();
    }
    __syncthreads();
}

// ---------------- 8-block group barrier (per recurrent step) ----------------
__device__ __forceinline__ void groupbar(int g) {
    __syncthreads();
    if (threadIdx.x == 0) {
        volatile unsigned* vg = &g_ggen[g * 32];
        unsigned gen = *vg;
        __threadfence();                       // release
        if (atomicAdd(&g_gcnt[g * 32], 1u) == 7u) {
            g_gcnt[g * 32] = 0;
            __threadfence();
            *vg = gen + 1;
        } else {
            while (*vg == gen) { __nanosleep(20); }
        }
        __threadfence();                       // acquire: invalidate L1
    }
    __syncthreads();
}

// ---------------- fast activations ----------------
__device__ __forceinline__ float sigf(float x) {
    return __fdividef(1.f, 1.f + __expf(-x));
}
__device__ __forceinline__ float tanhfast(float x) {
    return 1.f - __fdividef(2.f, __expf(2.f * x) + 1.f);
}

// ---------------- per-phase weight packing into smem ----------------
// rows [rowBase .. rowBase+Kin+H): first Kin rows = Wih, next H rows = Whh,
// packed [row][jloc*4+gate] for this block's 16 j's.
__device__ void pack_cell(float* __restrict__ s_w, float* __restrict__ s_bias,
                          const float* __restrict__ wih, const float* __restrict__ whh,
                          const float* __restrict__ bih, const float* __restrict__ bhh,
                          int Kin, int j0, int rowBase, int biasSlot)
{
    int total = (Kin + Hn) * 64;
    for (int e = threadIdx.x; e < total; e += NTHR) {
        int row = e >> 6, c = e & 63;
        int j = j0 + (c >> 2), g = c & 3;
        float v = (row < Kin) ? wih[(g * Hn + j) * Kin + row]
                              : whh[(g * Hn + j) * Hn + (row - Kin)];
        s_w[(size_t)(rowBase + row) * 64 + c] = v;
    }
    for (int e = threadIdx.x; e < 64; e += NTHR) {
        int j = j0 + (e >> 2), g = e & 3;
        s_bias[biasSlot * 64 + e] = bih[g * Hn + j] + bhh[g * Hn + j];
    }
}

struct Chunk { const float* src; long str; int kc; int wrow; };

// ---------------- fused LSTM cell tile ----------------
// Tile: BT b-rows x 16 j's with 512 threads. lane = b, warp = j (weight loads
// broadcast). Each thread owns NB (b,j) pairs & all 4 gates. Activations staged
// [b][kk]; 128-wide chunks are copied global->shared with cp.async, double
// buffered, so the copy of chunk i+1 overlaps the compute of chunk i.
template<int BT, int NB>
__device__ void cell_tile(float* __restrict__ s_w, float* __restrict__ s_a,
                          const float* __restrict__ s_bias,
                          int b0, int j0g,
                          const float* __restrict__ A, long aStr, long aOff, int Kin, int rowBase,
                          const float* __restrict__ hsrc, float* __restrict__ hdst,
                          float* __restrict__ cst, float* __restrict__ yout, int yStr)
{
    const int tid  = threadIdx.x;
    const int lane = tid & 31;
    const int jloc = tid >> 5;            // 0..15
    const int jgl  = j0g + jloc;
    const unsigned sa0 = (unsigned)__cvta_generic_to_shared(s_a);

    ull accL[NB], accH[NB];               // packed (i,f) and (g,o)
    {
        ull bL = *(const ull*)&s_bias[jloc * 4];
        ull bH = *(const ull*)&s_bias[jloc * 4 + 2];
#pragma unroll
        for (int i = 0; i < NB; i++) { accL[i] = bL; accH[i] = bH; }
    }

    // ---- build flat chunk list: seg0 (input) then seg1 (recurrent h) ----
    Chunk ch[3]; int nch = 0;
    for (int k0 = 0; k0 < Kin; k0 += CHK) {
        int kc = (Kin - k0 < CHK) ? (Kin - k0) : CHK;
        ch[nch].src = A + (long)b0 * aStr + aOff + k0;
        ch[nch].str = aStr; ch[nch].kc = kc; ch[nch].wrow = rowBase + k0;
        nch++;
    }
    ch[nch].src = hsrc + (long)b0 * Hn;
    ch[nch].str = Hn; ch[nch].kc = CHK; ch[nch].wrow = rowBase + Kin;
    nch++;

    // async staging of one 128-wide chunk into buffer `buf` (src/dst 16B aligned)
    auto stage_async = [&](const Chunk& c, int buf) {
#pragma unroll
        for (int u = 0; u < BT * 32 / NTHR; u++) {
            int q = tid + u * NTHR;       // quad index: b = q>>5, kq = q&31
            int b = q >> 5, kq = q & 31;
            cp16(sa0 + (unsigned)(buf * SA_FLOATS + b * STRD + kq * 4) * 4u,
                 c.src + (long)b * c.str + kq * 4);
        }
        CP_COMMIT();
    };
    // scalar staging for small chunks (K = 6 or 3; only ever chunk 0)
    auto stage_small = [&](const Chunk& c, int buf) {
        for (int idx = tid; idx < BT * c.kc; idx += NTHR) {
            int b = idx / c.kc, kk = idx - b * c.kc;
            s_a[buf * SA_FLOATS + b * STRD + kk] = c.src[(long)b * c.str + kk];
        }
    };

    // chunk 0 into buffer 0
    if (ch[0].kc == CHK) { stage_async(ch[0], 0); CP_WAIT0(); }
    else                 { stage_small(ch[0], 0); }
    __syncthreads();

#pragma unroll 1
    for (int i = 0; i < nch; i++) {
        if (i + 1 < nch) stage_async(ch[i + 1], (i + 1) & 1);   // overlaps compute

        const int kc = ch[i].kc;
        const float* wp = s_w + (size_t)ch[i].wrow * 64 + jloc * 4;
        const float* ab = s_a + (i & 1) * SA_FLOATS;
        if (kc == CHK) {
            // quad path: 4 k's per LDS.128 activation load
#pragma unroll 2
            for (int kq = 0; kq < CHK; kq += 4) {
                float4 av[NB];
#pragma unroll
                for (int n = 0; n < NB; n++)
                    av[n] = *(const float4*)&ab[(lane + 32 * n) * STRD + kq];
#pragma unroll
                for (int t = 0; t < 4; t++) {
                    ulonglong2 w = *(const ulonglong2*)(wp + (size_t)(kq + t) * 64);
#pragma unroll
                    for (int n = 0; n < NB; n++) {
                        float a = (t == 0) ? av[n].x : (t == 1) ? av[n].y
                                : (t == 2) ? av[n].z : av[n].w;
                        ull a2; asm("mov.b64 %0,{%1,%1};" : "=l"(a2) : "f"(a));
                        asm("fma.rn.f32x2 %0,%1,%2,%0;" : "+l"(accL[n]) : "l"(a2), "l"(w.x));
                        asm("fma.rn.f32x2 %0,%1,%2,%0;" : "+l"(accH[n]) : "l"(a2), "l"(w.y));
                    }
                }
            }
        } else {
            // scalar tail (K = 6 or 3)
            for (int kk = 0; kk < kc; kk++) {
                ulonglong2 w = *(const ulonglong2*)(wp + (size_t)kk * 64);
#pragma unroll
                for (int n = 0; n < NB; n++) {
                    float a = ab[(lane + 32 * n) * STRD + kk];
                    ull a2; asm("mov.b64 %0,{%1,%1};" : "=l"(a2) : "f"(a));
                    asm("fma.rn.f32x2 %0,%1,%2,%0;" : "+l"(accL[n]) : "l"(a2), "l"(w.x));
                    asm("fma.rn.f32x2 %0,%1,%2,%0;" : "+l"(accH[n]) : "l"(a2), "l"(w.y));
                }
            }
        }

        if (i + 1 < nch) { CP_WAIT0(); __syncthreads(); }
    }

    // gate update — thread exclusively owns (b, jgl)
#pragma unroll
    for (int i = 0; i < NB; i++) {
        float gi, gf, gg, go;
        asm("mov.b64 {%0,%1},%2;" : "=f"(gi), "=f"(gf) : "l"(accL[i]));
        asm("mov.b64 {%0,%1},%2;" : "=f"(gg), "=f"(go) : "l"(accH[i]));
        int b = b0 + lane + 32 * i;
        long ci = (long)b * Hn + jgl;
        float cold = cst[ci];
        float cn = sigf(gf) * cold + sigf(gi) * tanhfast(gg);
        float hn = sigf(go) * tanhfast(cn);
        cst[ci]  = cn;
        hdst[ci] = hn;
        if (yout) yout[(long)b * yStr + jgl] = hn;
    }
}

// ---------------- the persistent kernel ----------------
__global__ void __launch_bounds__(NTHR, 1) orbit_kernel(Params P)
{
    extern __shared__ float smem[];
    float* s_w    = smem;
    float* s_a    = smem + SW_FLOATS;
    float* s_bias = smem + SB_OFF;

    const int tid  = threadIdx.x;
    const int bid  = blockIdx.x;
    const int gtid = bid * NTHR + tid;
    const int gstr = NBLK * NTHR;

    // ===== Phase 0: zero encoder states =====
    {
        float* h0 = &g_h[0][0][0][0];
        float* c0 = &g_c[0][0][0];
        for (int e = gtid; e < 4 * Bn * Hn; e += gstr) { h0[e] = 0.f; c0[e] = 0.f; }
    }
    gbar();

    // ===== Encoder: group of 8 blocks covers (dir, 64-b tile); block owns 16 j =====
    const int dir = bid >> 6;
    const int btE = (bid >> 3) & 7;
    const int jbE = bid & 7;
    const int b0E = btE * 64;
    const int j0E = jbE * 16;

#pragma unroll 1
    for (int layer = 0; layer < 2; layer++) {
        int st  = layer * 2 + dir;
        if (bid < 128) {
            int kin = layer ? 2 * Hn : INn;
            pack_cell(s_w, s_bias, P.wih[st], P.whh[st], P.bih[st], P.bhh[st], kin, j0E, 0, 0);
        }
        __syncthreads();
#pragma unroll 1
        for (int s = 0; s < Tn; s++) {
            int cur = s & 1, nxt = cur ^ 1;
            if (bid < 128) {
                int t = dir ? (Tn - 1 - s) : s;
                if (layer == 0) {
                    cell_tile<64, 2>(s_w, s_a, s_bias, b0E, j0E,
                        P.x, (long)Tn * INn, (long)t * INn, INn, 0,
                        &g_h[cur][st][0][0], &g_h[nxt][st][0][0], &g_c[st][0][0],
                        g_y0 + (size_t)t * Bn * 2 * Hn + dir * Hn, 2 * Hn);
                } else {
                    cell_tile<64, 2>(s_w, s_a, s_bias, b0E, j0E,
                        g_y0 + (size_t)t * Bn * 2 * Hn, (long)(2 * Hn), 0L, 2 * Hn, 0,
                        &g_h[cur][st][0][0], &g_h[nxt][st][0][0], &g_c[st][0][0],
                        nullptr, 0);
                }
                groupbar(bid >> 3);   // only the 8 j-blocks of (dir,b-tile) couple
            }
        }
        gbar();                       // layer boundary: y0 / final states global
    }

    // ===== Bridge: h_dec/c_dec + start token (final enc states in buffer 0) =====
    {
        for (int idx = gtid; idx < (1 << 18); idx += gstr) {
            int j   = idx & (Hn - 1);
            int b   = (idx >> 7) & (Bn - 1);
            int l   = (idx >> 16) & 1;
            int typ = idx >> 17;
            const float* W    = typ ? P.brc_W : P.brh_W;
            const float* bias = typ ? P.brc_b : P.brh_b;
            const float* srcF = typ ? &g_c[2 * l][0][0] : &g_h[0][2 * l][0][0];
            const float* srcB = typ ? &g_c[2 * l + 1][0][0] : &g_h[0][2 * l + 1][0][0];
            const float* wr = &W[j * 2 * Hn];
            float acc = bias[j];
#pragma unroll 4
            for (int k = 0; k < Hn; k++) acc += srcF[b * Hn + k] * wr[k];
#pragma unroll 4
            for (int k = 0; k < Hn; k++) acc += srcB[b * Hn + k] * wr[Hn + k];
            if (typ) g_c[4 + l][b][j] = acc;
            else     g_h[0][4 + l][b][j] = acc;
        }
        for (int idx = gtid; idx < Bn * OUTn; idx += gstr)
            g_xin[idx] = P.start[idx % OUTn];
    }
    gbar();

    // ===== Decoder: group of 8 blocks covers 32-b tile; block owns 16 j =====
    const int btD = bid >> 3;          // 0..15
    const int jbD = bid & 7;
    const int b0D = btD * 32;
    const int j0D = jbD * 16;

    if (bid < 128) {
        pack_cell(s_w, s_bias, P.wih[4], P.whh[4], P.bih[4], P.bhh[4], OUTn, j0D, 0,   0);
        pack_cell(s_w, s_bias, P.wih[5], P.whh[5], P.bih[5], P.bhh[5], Hn,   j0D, 131, 1);
    }
    __syncthreads();

#pragma unroll 1
    for (int s = 0; s < HORn; s++) {
        int cur = s & 1, nxt = cur ^ 1;
        if (bid < 128) {
            // cell 0: input = previous prediction (K=3) + own h (K=128)
            cell_tile<32, 1>(s_w, s_a, s_bias, b0D, j0D,
                g_xin, (long)OUTn, 0L, OUTn, 0,
                &g_h[cur][4][0][0], &g_h[nxt][4][0][0], &g_c[4][0][0], nullptr, 0);
            groupbar(btD);

            // cell 1: input = cell0's new h (K=128) + own h (K=128)
            cell_tile<32, 1>(s_w, s_a, s_bias + 64, b0D, j0D,
                &g_h[nxt][4][0][0], (long)Hn, 0L, Hn, 131,
                &g_h[cur][5][0][0], &g_h[nxt][5][0][0], &g_c[5][0][0], nullptr, 0);
            groupbar(btD);

            // prediction head: group's 96 (b,o) dots spread 12 warps per block
            {
                int w = tid >> 5, lane = tid & 31;
                if (w < 12) {
                    int oi = jbD * 12 + w;              // 0..95 within group
                    int b  = b0D + oi / 3;
                    int o  = oi - (oi / 3) * 3;
                    float4 hv = ((const float4*)&g_h[nxt][5][b][0])[lane];
                    float4 wv = ((const float4*)&P.out_W[o * Hn])[lane];
                    float v = hv.x * wv.x + hv.y * wv.y + hv.z * wv.z + hv.w * wv.w;
#pragma unroll
                    for (int d = 16; d; d >>= 1) v += __shfl_down_sync(0xffffffffu, v, d);
                    if (lane == 0) {
                        v += P.out_b[o];
                        P.out[(size_t)b * HORn * OUTn + (size_t)s * OUTn + o] = v;
                        g_xin[b * OUTn + o] = v;
                    }
                }
            }
            groupbar(btD);
        }
    }
}

// ---------------- launch ----------------
extern "C" void kernel_launch(void* const* d_in, const int* in_sizes, int n_in,
                              void* d_out, int out_size)
{
    (void)in_sizes; (void)n_in; (void)out_size;
    Params P;
    P.x = (const float*)d_in[0];
    const int base[6] = {1, 5, 9, 13, 21, 25};   // e0f,e0b,e1f,e1b,d0,d1
    for (int i = 0; i < 6; i++) {
        P.wih[i] = (const float*)d_in[base[i] + 0];
        P.whh[i] = (const float*)d_in[base[i] + 1];
        P.bih[i] = (const float*)d_in[base[i] + 2];
        P.bhh[i] = (const float*)d_in[base[i] + 3];
    }
    P.brh_W = (const float*)d_in[17];
    P.brh_b = (const float*)d_in[18];
    P.brc_W = (const float*)d_in[19];
    P.brc_b = (const float*)d_in[20];
    P.out_W = (const float*)d_in[29];
    P.out_b = (const float*)d_in[30];
    P.start = (const float*)d_in[31];
    P.out   = (float*)d_out;

    cudaFuncSetAttribute(orbit_kernel, cudaFuncAttributeMaxDynamicSharedMemorySize,
                         SMEM_BYTES);
    orbit_kernel<<<NBLK, NTHR, SMEM_BYTES>>>(P);
}

// round 11
// speedup vs baseline: 1.5901x; 1.0390x over previous
#include <cuda_runtime.h>

#define Tn   720
#define Bn   512
#define INn  6
#define Hn   128
#define OUTn 3
#define HORn 360
#define NBLK 148
#define NTHR 512
#define CHK  128
#define STRD 132   // [b][kk] staging stride: 33*16B -> conflict-free LDS.128

typedef unsigned long long ull;

struct Params {
    const float* x;
    const float* wih[6];   // e0f,e0b,e1f,e1b,d0,d1
    const float* whh[6];
    const float* bih[6];
    const float* bhh[6];
    const float* brh_W; const float* brh_b;
    const float* brc_W; const float* brc_b;
    const float* out_W; const float* out_b;
    const float* start;
    float* out;
};

// ---------------- scratch (device globals; no allocation allowed) ----------------
__device__ float g_y0[(size_t)Tn * Bn * 2 * Hn];      // encoder layer0 outputs [t][b][256]
__device__ float g_h[2][6][Bn][Hn];                   // double-buffered hidden state
__device__ float g_c[6][Bn][Hn];                      // cell state (in-place)
__device__ float g_xin[Bn * OUTn];                    // decoder autoregressive input
__device__ unsigned g_barcnt = 0;
__device__ unsigned g_bargen = 0;
__device__ unsigned g_gcnt[16 * 32];                  // monotonic arrival counts, 128B apart
__device__ unsigned g_ggen[16 * 32];                  // published completed-round counts

// ---------------- shared-memory layout (dynamic, ~167KB) ----------------
#define SW_FLOATS (387 * 64)            // weights [row][jloc*4+gate], 16 j per block
#define SA_FLOATS (64 * STRD)           // one staging buffer: 64 b x 128 kk (+pad)
#define SB_OFF    (SW_FLOATS + 2 * SA_FLOATS)
#define SMEM_BYTES ((SB_OFF + 128) * 4)

// ---------------- cp.async helpers ----------------
__device__ __forceinline__ void cp16(unsigned saddr, const float* g) {
    asm volatile("cp.async.ca.shared.global [%0], [%1], 16;" :: "r"(saddr), "l"(g));
}
#define CP_COMMIT() asm volatile("cp.async.commit_group;" ::: "memory")
#define CP_WAIT0()  asm volatile("cp.async.wait_group 0;" ::: "memory")

// ---------------- full grid barrier (phase boundaries only) ----------------
__device__ __forceinline__ void gbar() {
    __syncthreads();
    if (threadIdx.x == 0) {
        volatile unsigned* vg = &g_bargen;
        unsigned gen = *vg;
        __threadfence();
        if (atomicAdd(&g_barcnt, 1u) == NBLK - 1) {
            g_barcnt = 0;
            __threadfence();
            *vg = gen + 1;
        } else {
            while (*vg == gen) { __nanosleep(32); }
        }
        __threadfence();
    }
    __syncthreads();
}

// ---------------- split 8-block group barrier (monotonic rounds) ----------------
// arrive: non-blocking. 8th arrival of a round publishes the round count.
// wait(target): block until `target` rounds completed. Every arrive in the
// program is preceded by a wait on the previous round, so publishes are
// strictly serialized (no stale overwrite). Counters are RESET at each launch
// in Phase 0 (before the first gbar) — kernel_launch must be deterministic
// across graph replays.
__device__ __forceinline__ void gb_arrive(int g) {
    __syncthreads();                           // all epilogue stores issued
    if (threadIdx.x == 0) {
        __threadfence();                       // release h/xin stores
        unsigned old = atomicAdd(&g_gcnt[g * 32], 1u);
        if (((old + 1) & 7u) == 0u) {          // 8th arrival of this round
            __threadfence();
            *(volatile unsigned*)&g_ggen[g * 32] = (old + 1) >> 3;
        }
    }
}
__device__ __forceinline__ void gb_wait(int g, unsigned target) {
    if (threadIdx.x == 0) {
        volatile unsigned* vg = &g_ggen[g * 32];
        while (*vg < target) { __nanosleep(20); }
        __threadfence();                       // acquire: invalidate L1
    }
    __syncthreads();
}

// ---------------- fast activations ----------------
__device__ __forceinline__ float sigf(float x) {
    return __fdividef(1.f, 1.f + __expf(-x));
}
__device__ __forceinline__ float tanhfast(float x) {
    return 1.f - __fdividef(2.f, __expf(2.f * x) + 1.f);
}

// ---------------- per-phase weight packing into smem ----------------
// rows [rowBase .. rowBase+Kin+H): first Kin rows = Wih, next H rows = Whh,
// packed [row][jloc*4+gate] for this block's 16 j's.
__device__ void pack_cell(float* __restrict__ s_w, float* __restrict__ s_bias,
                          const float* __restrict__ wih, const float* __restrict__ whh,
                          const float* __restrict__ bih, const float* __restrict__ bhh,
                          int Kin, int j0, int rowBase, int biasSlot)
{
    int total = (Kin + Hn) * 64;
    for (int e = threadIdx.x; e < total; e += NTHR) {
        int row = e >> 6, c = e & 63;
        int j = j0 + (c >> 2), g = c & 3;
        float v = (row < Kin) ? wih[(g * Hn + j) * Kin + row]
                              : whh[(g * Hn + j) * Hn + (row - Kin)];
        s_w[(size_t)(rowBase + row) * 64 + c] = v;
    }
    for (int e = threadIdx.x; e < 64; e += NTHR) {
        int j = j0 + (e >> 2), g = e & 3;
        s_bias[biasSlot * 64 + e] = bih[g * Hn + j] + bhh[g * Hn + j];
    }
}

struct Chunk { const float* src; long str; int kc; int wrow; };

// ---------------- fused LSTM cell tile ----------------
// Tile: BT b-rows x 16 j's with 512 threads. lane = b, warp = j.
// Chunk list ordered so the DEPENDENT chunk (needs the group barrier) is LAST:
//   encoder (hFirst=false): [A chunks..., h]   (dep = recurrent h)
//   decoder (hFirst=true):  [own-h, A chunk]   (dep = A: xin or peer h)
// gb_wait(waitRound) is issued just before staging the dependent chunk, so the
// barrier hides behind all earlier independent compute.
template<int BT, int NB>
__device__ void cell_tile(float* __restrict__ s_w, float* __restrict__ s_a,
                          const float* __restrict__ s_bias,
                          int b0, int j0g,
                          const float* __restrict__ A, long aStr, long aOff, int Kin, int rowBase,
                          const float* __restrict__ hsrc, float* __restrict__ hdst,
                          float* __restrict__ cst, float* __restrict__ yout, int yStr,
                          int g, unsigned waitRound, bool hFirst)
{
    const int tid  = threadIdx.x;
    const int lane = tid & 31;
    const int jloc = tid >> 5;            // 0..15
    const int jgl  = j0g + jloc;
    const unsigned sa0 = (unsigned)__cvta_generic_to_shared(s_a);

    ull accL[NB], accH[NB];               // packed (i,f) and (g,o)
    {
        ull bL = *(const ull*)&s_bias[jloc * 4];
        ull bH = *(const ull*)&s_bias[jloc * 4 + 2];
#pragma unroll
        for (int i = 0; i < NB; i++) { accL[i] = bL; accH[i] = bH; }
    }

    // ---- build chunk list, dependent chunk last ----
    Chunk ch[3]; int nch = 0;
    if (hFirst) {
        ch[nch++] = { hsrc + (long)b0 * Hn, (long)Hn, CHK, rowBase + Kin };
        // decoder A is always a single chunk (K = 3 or 128)
        ch[nch++] = { A + (long)b0 * aStr + aOff, aStr,
                      (Kin < CHK) ? Kin : CHK, rowBase };
    } else {
        for (int k0 = 0; k0 < Kin; k0 += CHK) {
            int kc = (Kin - k0 < CHK) ? (Kin - k0) : CHK;
            ch[nch].src = A + (long)b0 * aStr + aOff + k0;
            ch[nch].str = aStr; ch[nch].kc = kc; ch[nch].wrow = rowBase + k0;
            nch++;
        }
        ch[nch++] = { hsrc + (long)b0 * Hn, (long)Hn, CHK, rowBase + Kin };
    }

    // async staging of one 128-wide chunk into buffer `buf` (src/dst 16B aligned)
    auto stage_async = [&](const Chunk& c, int buf) {
#pragma unroll
        for (int u = 0; u < BT * 32 / NTHR; u++) {
            int q = tid + u * NTHR;       // quad index: b = q>>5, kq = q&31
            int b = q >> 5, kq = q & 31;
            cp16(sa0 + (unsigned)(buf * SA_FLOATS + b * STRD + kq * 4) * 4u,
                 c.src + (long)b * c.str + kq * 4);
        }
        CP_COMMIT();
    };
    // scalar staging for small chunks (K = 6 or 3)
    auto stage_small = [&](const Chunk& c, int buf) {
        for (int idx = tid; idx < BT * c.kc; idx += NTHR) {
            int b = idx / c.kc, kk = idx - b * c.kc;
            s_a[buf * SA_FLOATS + b * STRD + kk] = c.src[(long)b * c.str + kk];
        }
    };

    // chunk 0 into buffer 0 (always independent — no wait needed)
    if (ch[0].kc == CHK) { stage_async(ch[0], 0); CP_WAIT0(); }
    else                 { stage_small(ch[0], 0); }
    __syncthreads();

#pragma unroll 1
    for (int i = 0; i < nch; i++) {
        if (i + 1 < nch) {
            if (i + 1 == nch - 1) gb_wait(g, waitRound);   // dep chunk: wait first
            if (ch[i + 1].kc == CHK) stage_async(ch[i + 1], (i + 1) & 1);
            else                     stage_small(ch[i + 1], (i + 1) & 1);
        }

        const int kc = ch[i].kc;
        const float* wp = s_w + (size_t)ch[i].wrow * 64 + jloc * 4;
        const float* ab = s_a + (i & 1) * SA_FLOATS;
        if (kc == CHK) {
            // quad path: 4 k's per LDS.128 activation load
#pragma unroll 2
            for (int kq = 0; kq < CHK; kq += 4) {
                float4 av[NB];
#pragma unroll
                for (int n = 0; n < NB; n++)
                    av[n] = *(const float4*)&ab[(lane + 32 * n) * STRD + kq];
#pragma unroll
                for (int t = 0; t < 4; t++) {
                    ulonglong2 w = *(const ulonglong2*)(wp + (size_t)(kq + t) * 64);
#pragma unroll
                    for (int n = 0; n < NB; n++) {
                        float a = (t == 0) ? av[n].x : (t == 1) ? av[n].y
                                : (t == 2) ? av[n].z : av[n].w;
                        ull a2; asm("mov.b64 %0,{%1,%1};" : "=l"(a2) : "f"(a));
                        asm("fma.rn.f32x2 %0,%1,%2,%0;" : "+l"(accL[n]) : "l"(a2), "l"(w.x));
                        asm("fma.rn.f32x2 %0,%1,%2,%0;" : "+l"(accH[n]) : "l"(a2), "l"(w.y));
                    }
                }
            }
        } else {
            // scalar tail (K = 6 or 3)
            for (int kk = 0; kk < kc; kk++) {
                ulonglong2 w = *(const ulonglong2*)(wp + (size_t)kk * 64);
#pragma unroll
                for (int n = 0; n < NB; n++) {
                    float a = ab[(lane + 32 * n) * STRD + kk];
                    ull a2; asm("mov.b64 %0,{%1,%1};" : "=l"(a2) : "f"(a));
                    asm("fma.rn.f32x2 %0,%1,%2,%0;" : "+l"(accL[n]) : "l"(a2), "l"(w.x));
                    asm("fma.rn.f32x2 %0,%1,%2,%0;" : "+l"(accH[n]) : "l"(a2), "l"(w.y));
                }
            }
        }

        if (i + 1 < nch) { CP_WAIT0(); __syncthreads(); }
    }

    // gate update — thread exclusively owns (b, jgl)
#pragma unroll
    for (int i = 0; i < NB; i++) {
        float gi, gf, gg, go;
        asm("mov.b64 {%0,%1},%2;" : "=f"(gi), "=f"(gf) : "l"(accL[i]));
        asm("mov.b64 {%0,%1},%2;" : "=f"(gg), "=f"(go) : "l"(accH[i]));
        int b = b0 + lane + 32 * i;
        long ci = (long)b * Hn + jgl;
        float cold = cst[ci];
        float cn = sigf(gf) * cold + sigf(gi) * tanhfast(gg);
        float hn = sigf(go) * tanhfast(cn);
        cst[ci]  = cn;
        hdst[ci] = hn;
        if (yout) yout[(long)b * yStr + jgl] = hn;
    }
}

// ---------------- the persistent kernel ----------------
__global__ void __launch_bounds__(NTHR, 1) orbit_kernel(Params P)
{
    extern __shared__ float smem[];
    float* s_w    = smem;
    float* s_a    = smem + SW_FLOATS;
    float* s_bias = smem + SB_OFF;

    const int tid  = threadIdx.x;
    const int bid  = blockIdx.x;
    const int gtid = bid * NTHR + tid;
    const int gstr = NBLK * NTHR;

    // ===== Phase 0: zero encoder states AND reset group-barrier state =====
    // (g_gcnt/g_ggen are monotonic within a launch; they MUST start at 0 every
    //  launch or graph replays see stale published rounds -> races.)
    {
        float* h0 = &g_h[0][0][0][0];
        float* c0 = &g_c[0][0][0];
        for (int e = gtid; e < 4 * Bn * Hn; e += gstr) { h0[e] = 0.f; c0[e] = 0.f; }
        for (int e = gtid; e < 16 * 32; e += gstr) { g_gcnt[e] = 0u; g_ggen[e] = 0u; }
    }
    gbar();

    // ===== Encoder: group of 8 blocks covers (dir, 64-b tile); block owns 16 j =====
    const int dir = bid >> 6;
    const int btE = (bid >> 3) & 7;
    const int jbE = bid & 7;
    const int b0E = btE * 64;
    const int j0E = jbE * 16;
    const int grp = bid >> 3;            // 0..15 (same partition for enc & dec)
    unsigned done = 0;                   // this block's completed group rounds

#pragma unroll 1
    for (int layer = 0; layer < 2; layer++) {
        int st  = layer * 2 + dir;
        if (bid < 128) {
            int kin = layer ? 2 * Hn : INn;
            pack_cell(s_w, s_bias, P.wih[st], P.whh[st], P.bih[st], P.bhh[st], kin, j0E, 0, 0);
        }
        __syncthreads();
#pragma unroll 1
        for (int s = 0; s < Tn; s++) {
            int cur = s & 1, nxt = cur ^ 1;
            if (bid < 128) {
                int t = dir ? (Tn - 1 - s) : s;
                if (layer == 0) {
                    cell_tile<64, 2>(s_w, s_a, s_bias, b0E, j0E,
                        P.x, (long)Tn * INn, (long)t * INn, INn, 0,
                        &g_h[cur][st][0][0], &g_h[nxt][st][0][0], &g_c[st][0][0],
                        g_y0 + (size_t)t * Bn * 2 * Hn + dir * Hn, 2 * Hn,
                        grp, done, false);
                } else {
                    cell_tile<64, 2>(s_w, s_a, s_bias, b0E, j0E,
                        g_y0 + (size_t)t * Bn * 2 * Hn, (long)(2 * Hn), 0L, 2 * Hn, 0,
                        &g_h[cur][st][0][0], &g_h[nxt][st][0][0], &g_c[st][0][0],
                        nullptr, 0,
                        grp, done, false);
                }
                gb_arrive(grp); done++;
            }
        }
        gbar();                       // layer boundary: y0 / final states global
    }

    // ===== Bridge: h_dec/c_dec + start token (final enc states in buffer 0) =====
    {
        for (int idx = gtid; idx < (1 << 18); idx += gstr) {
            int j   = idx & (Hn - 1);
            int b   = (idx >> 7) & (Bn - 1);
            int l   = (idx >> 16) & 1;
            int typ = idx >> 17;
            const float* W    = typ ? P.brc_W : P.brh_W;
            const float* bias = typ ? P.brc_b : P.brh_b;
            const float* srcF = typ ? &g_c[2 * l][0][0] : &g_h[0][2 * l][0][0];
            const float* srcB = typ ? &g_c[2 * l + 1][0][0] : &g_h[0][2 * l + 1][0][0];
            const float* wr = &W[j * 2 * Hn];
            float acc = bias[j];
#pragma unroll 4
            for (int k = 0; k < Hn; k++) acc += srcF[b * Hn + k] * wr[k];
#pragma unroll 4
            for (int k = 0; k < Hn; k++) acc += srcB[b * Hn + k] * wr[Hn + k];
            if (typ) g_c[4 + l][b][j] = acc;
            else     g_h[0][4 + l][b][j] = acc;
        }
        for (int idx = gtid; idx < Bn * OUTn; idx += gstr)
            g_xin[idx] = P.start[idx % OUTn];
    }
    gbar();

    // ===== Decoder: group of 8 blocks covers 32-b tile; block owns 16 j =====
    const int btD = bid >> 3;          // 0..15
    const int jbD = bid & 7;
    const int b0D = btD * 32;
    const int j0D = jbD * 16;

    if (bid < 128) {
        pack_cell(s_w, s_bias, P.wih[4], P.whh[4], P.bih[4], P.bhh[4], OUTn, j0D, 0,   0);
        pack_cell(s_w, s_bias, P.wih[5], P.whh[5], P.bih[5], P.bhh[5], Hn,   j0D, 131, 1);
    }
    __syncthreads();

#pragma unroll 1
    for (int s = 0; s < HORn; s++) {
        int cur = s & 1, nxt = cur ^ 1;
        if (bid < 128) {
            // cell 0: indep = own h (K=128); dep = xin (K=3, from prev head)
            cell_tile<32, 1>(s_w, s_a, s_bias, b0D, j0D,
                g_xin, (long)OUTn, 0L, OUTn, 0,
                &g_h[cur][4][0][0], &g_h[nxt][4][0][0], &g_c[4][0][0], nullptr, 0,
                grp, done, true);
            gb_arrive(grp); done++;

            // cell 1: indep = own h5 (K=128); dep = cell0's new h4 (K=128)
            cell_tile<32, 1>(s_w, s_a, s_bias + 64, b0D, j0D,
                &g_h[nxt][4][0][0], (long)Hn, 0L, Hn, 131,
                &g_h[cur][5][0][0], &g_h[nxt][5][0][0], &g_c[5][0][0], nullptr, 0,
                grp, done, true);
            gb_arrive(grp); done++;

            // prediction head: needs all 128 j of h5 -> blocking wait
            gb_wait(grp, done);
            {
                int w = tid >> 5, lane = tid & 31;
                if (w < 12) {
                    int oi = jbD * 12 + w;              // 0..95 within group
                    int b  = b0D + oi / 3;
                    int o  = oi - (oi / 3) * 3;
                    float4 hv = ((const float4*)&g_h[nxt][5][b][0])[lane];
                    float4 wv = ((const float4*)&P.out_W[o * Hn])[lane];
                    float v = hv.x * wv.x + hv.y * wv.y + hv.z * wv.z + hv.w * wv.w;
#pragma unroll
                    for (int d = 16; d; d >>= 1) v += __shfl_down_sync(0xffffffffu, v, d);
                    if (lane == 0) {
                        v += P.out_b[o];
                        P.out[(size_t)b * HORn * OUTn + (size_t)s * OUTn + o] = v;
                        g_xin[b * OUTn + o] = v;
                    }
                }
            }
            gb_arrive(grp); done++;
        }
    }
}

// ---------------- launch ----------------
extern "C" void kernel_launch(void* const* d_in, const int* in_sizes, int n_in,
                              void* d_out, int out_size)
{
    (void)in_sizes; (void)n_in; (void)out_size;
    Params P;
    P.x = (const float*)d_in[0];
    const int base[6] = {1, 5, 9, 13, 21, 25};   // e0f,e0b,e1f,e1b,d0,d1
    for (int i = 0; i < 6; i++) {
        P.wih[i] = (const float*)d_in[base[i] + 0];
        P.whh[i] = (const float*)d_in[base[i] + 1];
        P.bih[i] = (const float*)d_in[base[i] + 2];
        P.bhh[i] = (const float*)d_in[base[i] + 3];
    }
    P.brh_W = (const float*)d_in[17];
    P.brh_b = (const float*)d_in[18];
    P.brc_W = (const float*)d_in[19];
    P.brc_b = (const float*)d_in[20];
    P.out_W = (const float*)d_in[29];
    P.out_b = (const float*)d_in[30];
    P.start = (const float*)d_in[31];
    P.out   = (float*)d_out;

    cudaFuncSetAttribute(orbit_kernel, cudaFuncAttributeMaxDynamicSharedMemorySize,
                         SMEM_BYTES);
    orbit_kernel<<<NBLK, NTHR, SMEM_BYTES>>>(P);
}

// round 12
// speedup vs baseline: 1.6404x; 1.0317x over previous
#include <cuda_runtime.h>

#define Tn   720
#define Bn   512
#define INn  6
#define Hn   128
#define OUTn 3
#define HORn 360
#define NBLK 148
#define NTHR 512
#define CHK  128
#define STRD 132   // [b][kk] staging stride: 33*16B -> conflict-free LDS.128

typedef unsigned long long ull;

struct Params {
    const float* x;
    const float* wih[6];   // e0f,e0b,e1f,e1b,d0,d1
    const float* whh[6];
    const float* bih[6];
    const float* bhh[6];
    const float* brh_W; const float* brh_b;
    const float* brc_W; const float* brc_b;
    const float* out_W; const float* out_b;
    const float* start;
    float* out;
};

// ---------------- scratch (device globals; no allocation allowed) ----------------
__device__ float g_y0[(size_t)Tn * Bn * 2 * Hn];      // encoder layer0 outputs [t][b][256]
__device__ float g_h[2][6][Bn][Hn];                   // double-buffered hidden state
__device__ float g_c[6][Bn][Hn];                      // cell state (in-place)
__device__ float g_hp[2][16][8][32][OUTn];            // decoder head partials [parity][grp][jb][b][o]
__device__ unsigned g_barcnt = 0;
__device__ unsigned g_bargen = 0;
__device__ unsigned g_gcnt[16 * 32];                  // monotonic arrival counts, 128B apart
__device__ unsigned g_ggen[16 * 32];                  // published completed-round counts

// ---------------- shared-memory layout (dynamic, ~167KB) ----------------
#define SW_FLOATS (387 * 64)            // weights [row][jloc*4+gate], 16 j per block
#define SA_FLOATS (64 * STRD)           // one staging buffer: 64 b x 128 kk (+pad)
#define SB_OFF    (SW_FLOATS + 2 * SA_FLOATS)
#define SMEM_BYTES ((SB_OFF + 128) * 4)

// ---------------- cp.async helpers ----------------
__device__ __forceinline__ void cp16(unsigned saddr, const float* g) {
    asm volatile("cp.async.ca.shared.global [%0], [%1], 16;" :: "r"(saddr), "l"(g));
}
#define CP_COMMIT() asm volatile("cp.async.commit_group;" ::: "memory")
#define CP_WAIT0()  asm volatile("cp.async.wait_group 0;" ::: "memory")

// ---------------- full grid barrier (phase boundaries only) ----------------
__device__ __forceinline__ void gbar() {
    __syncthreads();
    if (threadIdx.x == 0) {
        volatile unsigned* vg = &g_bargen;
        unsigned gen = *vg;
        __threadfence();
        if (atomicAdd(&g_barcnt, 1u) == NBLK - 1) {
            g_barcnt = 0;
            __threadfence();
            *vg = gen + 1;
        } else {
            while (*vg == gen) { __nanosleep(32); }
        }
        __threadfence();
    }
    __syncthreads();
}

// ---------------- split 8-block group barrier (monotonic rounds) ----------------
// Counters RESET each launch in Phase 0 (graph-replay determinism).
__device__ __forceinline__ void gb_arrive(int g) {
    __syncthreads();                           // all epilogue stores issued
    if (threadIdx.x == 0) {
        __threadfence();                       // release h/partial stores
        unsigned old = atomicAdd(&g_gcnt[g * 32], 1u);
        if (((old + 1) & 7u) == 0u) {          // 8th arrival of this round
            __threadfence();
            *(volatile unsigned*)&g_ggen[g * 32] = (old + 1) >> 3;
        }
    }
}
__device__ __forceinline__ void gb_wait(int g, unsigned target) {
    if (threadIdx.x == 0) {
        volatile unsigned* vg = &g_ggen[g * 32];
        while (*vg < target) { __nanosleep(20); }
        __threadfence();                       // acquire: invalidate L1
    }
    __syncthreads();
}

// ---------------- fast activations ----------------
__device__ __forceinline__ float sigf(float x) {
    return __fdividef(1.f, 1.f + __expf(-x));
}
__device__ __forceinline__ float tanhfast(float x) {
    return 1.f - __fdividef(2.f, __expf(2.f * x) + 1.f);
}

// ---------------- per-phase weight packing into smem ----------------
__device__ void pack_cell(float* __restrict__ s_w, float* __restrict__ s_bias,
                          const float* __restrict__ wih, const float* __restrict__ whh,
                          const float* __restrict__ bih, const float* __restrict__ bhh,
                          int Kin, int j0, int rowBase, int biasSlot)
{
    int total = (Kin + Hn) * 64;
    for (int e = threadIdx.x; e < total; e += NTHR) {
        int row = e >> 6, c = e & 63;
        int j = j0 + (c >> 2), g = c & 3;
        float v = (row < Kin) ? wih[(g * Hn + j) * Kin + row]
                              : whh[(g * Hn + j) * Hn + (row - Kin)];
        s_w[(size_t)(rowBase + row) * 64 + c] = v;
    }
    for (int e = threadIdx.x; e < 64; e += NTHR) {
        int j = j0 + (e >> 2), g = e & 3;
        s_bias[biasSlot * 64 + e] = bih[g * Hn + j] + bhh[g * Hn + j];
    }
}

struct Chunk { const float* src; long str; int kc; int wrow; };

// ---------------- fused LSTM cell tile ----------------
// Tile: BT b-rows x 16 j's with 512 threads. lane = b, warp = j.
// Dependent chunk last; gb_wait just before staging it.
// xinMode: 0 = normal dep staging; 1 = dep = sum of 8 head partials (+out_b),
//          optional P.out write; 2 = dep = broadcast start token.
// hpOut/outW: if set, after the gate epilogue compute this block's head
// partials for its 16 j (cross-warp reduce via s_a buf0) into hpOut[b][o].
template<int BT, int NB>
__device__ void cell_tile(float* __restrict__ s_w, float* __restrict__ s_a,
                          const float* __restrict__ s_bias,
                          int b0, int j0g,
                          const float* __restrict__ A, long aStr, long aOff, int Kin, int rowBase,
                          const float* __restrict__ hsrc, float* __restrict__ hdst,
                          float* __restrict__ cst, float* __restrict__ yout, int yStr,
                          int g, unsigned waitRound, bool hFirst,
                          int xinMode, const float* __restrict__ hpIn,
                          const float* __restrict__ xvec, float* __restrict__ poutPrev,
                          float* __restrict__ hpOut, const float* __restrict__ outW)
{
    const int tid  = threadIdx.x;
    const int lane = tid & 31;
    const int jloc = tid >> 5;            // 0..15
    const int jgl  = j0g + jloc;
    const unsigned sa0 = (unsigned)__cvta_generic_to_shared(s_a);

    ull accL[NB], accH[NB];               // packed (i,f) and (g,o)
    {
        ull bL = *(const ull*)&s_bias[jloc * 4];
        ull bH = *(const ull*)&s_bias[jloc * 4 + 2];
#pragma unroll
        for (int i = 0; i < NB; i++) { accL[i] = bL; accH[i] = bH; }
    }

    // ---- build chunk list, dependent chunk last ----
    Chunk ch[3]; int nch = 0;
    if (hFirst) {
        ch[nch++] = { hsrc + (long)b0 * Hn, (long)Hn, CHK, rowBase + Kin };
        ch[nch++] = { A + (long)b0 * aStr + aOff, aStr,
                      (Kin < CHK) ? Kin : CHK, rowBase };
    } else {
        for (int k0 = 0; k0 < Kin; k0 += CHK) {
            int kc = (Kin - k0 < CHK) ? (Kin - k0) : CHK;
            ch[nch].src = A + (long)b0 * aStr + aOff + k0;
            ch[nch].str = aStr; ch[nch].kc = kc; ch[nch].wrow = rowBase + k0;
            nch++;
        }
        ch[nch++] = { hsrc + (long)b0 * Hn, (long)Hn, CHK, rowBase + Kin };
    }

    auto stage_async = [&](const Chunk& c, int buf) {
#pragma unroll
        for (int u = 0; u < BT * 32 / NTHR; u++) {
            int q = tid + u * NTHR;       // quad index: b = q>>5, kq = q&31
            int b = q >> 5, kq = q & 31;
            cp16(sa0 + (unsigned)(buf * SA_FLOATS + b * STRD + kq * 4) * 4u,
                 c.src + (long)b * c.str + kq * 4);
        }
        CP_COMMIT();
    };
    // scalar staging for small chunks (K = 6 or 3); handles xin modes
    auto stage_small = [&](const Chunk& c, int buf) {
        if (xinMode == 2) {
            for (int idx = tid; idx < BT * c.kc; idx += NTHR) {
                int b = idx / c.kc, kk = idx - b * c.kc;
                s_a[buf * SA_FLOATS + b * STRD + kk] = xvec[kk];
            }
        } else if (xinMode == 1) {
            for (int idx = tid; idx < BT * OUTn; idx += NTHR) {
                int b = idx / OUTn, o = idx - b * OUTn;
                float v = xvec[o];
#pragma unroll
                for (int jb = 0; jb < 8; jb++)
                    v += hpIn[(jb * 32 + b) * OUTn + o];
                s_a[buf * SA_FLOATS + b * STRD + o] = v;
                if (poutPrev)
                    poutPrev[(size_t)(b0 + b) * HORn * OUTn + o] = v;
            }
        } else {
            for (int idx = tid; idx < BT * c.kc; idx += NTHR) {
                int b = idx / c.kc, kk = idx - b * c.kc;
                s_a[buf * SA_FLOATS + b * STRD + kk] = c.src[(long)b * c.str + kk];
            }
        }
    };

    // chunk 0 into buffer 0 (always independent — no wait needed)
    if (ch[0].kc == CHK) { stage_async(ch[0], 0); CP_WAIT0(); }
    else                 { stage_small(ch[0], 0); }
    __syncthreads();

#pragma unroll 1
    for (int i = 0; i < nch; i++) {
        if (i + 1 < nch) {
            if (i + 1 == nch - 1) gb_wait(g, waitRound);   // dep chunk: wait first
            if (ch[i + 1].kc == CHK) stage_async(ch[i + 1], (i + 1) & 1);
            else                     stage_small(ch[i + 1], (i + 1) & 1);
        }

        const int kc = ch[i].kc;
        const float* wp = s_w + (size_t)ch[i].wrow * 64 + jloc * 4;
        const float* ab = s_a + (i & 1) * SA_FLOATS;
        if (kc == CHK) {
#pragma unroll 2
            for (int kq = 0; kq < CHK; kq += 4) {
                float4 av[NB];
#pragma unroll
                for (int n = 0; n < NB; n++)
                    av[n] = *(const float4*)&ab[(lane + 32 * n) * STRD + kq];
#pragma unroll
                for (int t = 0; t < 4; t++) {
                    ulonglong2 w = *(const ulonglong2*)(wp + (size_t)(kq + t) * 64);
#pragma unroll
                    for (int n = 0; n < NB; n++) {
                        float a = (t == 0) ? av[n].x : (t == 1) ? av[n].y
                                : (t == 2) ? av[n].z : av[n].w;
                        ull a2; asm("mov.b64 %0,{%1,%1};" : "=l"(a2) : "f"(a));
                        asm("fma.rn.f32x2 %0,%1,%2,%0;" : "+l"(accL[n]) : "l"(a2), "l"(w.x));
                        asm("fma.rn.f32x2 %0,%1,%2,%0;" : "+l"(accH[n]) : "l"(a2), "l"(w.y));
                    }
                }
            }
        } else {
            for (int kk = 0; kk < kc; kk++) {
                ulonglong2 w = *(const ulonglong2*)(wp + (size_t)kk * 64);
#pragma unroll
                for (int n = 0; n < NB; n++) {
                    float a = ab[(lane + 32 * n) * STRD + kk];
                    ull a2; asm("mov.b64 %0,{%1,%1};" : "=l"(a2) : "f"(a));
                    asm("fma.rn.f32x2 %0,%1,%2,%0;" : "+l"(accL[n]) : "l"(a2), "l"(w.x));
                    asm("fma.rn.f32x2 %0,%1,%2,%0;" : "+l"(accH[n]) : "l"(a2), "l"(w.y));
                }
            }
        }

        if (i + 1 < nch) { CP_WAIT0(); __syncthreads(); }
    }

    // gate update — thread exclusively owns (b, jgl)
    float hnKeep = 0.f;
#pragma unroll
    for (int i = 0; i < NB; i++) {
        float gi, gf, gg, go;
        asm("mov.b64 {%0,%1},%2;" : "=f"(gi), "=f"(gf) : "l"(accL[i]));
        asm("mov.b64 {%0,%1},%2;" : "=f"(gg), "=f"(go) : "l"(accH[i]));
        int b = b0 + lane + 32 * i;
        long ci = (long)b * Hn + jgl;
        float cold = cst[ci];
        float cn = sigf(gf) * cold + sigf(gi) * tanhfast(gg);
        float hn = sigf(go) * tanhfast(cn);
        cst[ci]  = cn;
        hdst[ci] = hn;
        hnKeep = hn;
        if (yout) yout[(long)b * yStr + jgl] = hn;
    }

    // head partials (decoder cell1 only; NB==1): this block's 16 j -> [32b][3o]
    if (hpOut) {
        __syncthreads();                       // s_a buf0 free for reduction
        s_a[(jloc * 32 + lane) * OUTn + 0] = hnKeep * outW[jgl];
        s_a[(jloc * 32 + lane) * OUTn + 1] = hnKeep * outW[Hn + jgl];
        s_a[(jloc * 32 + lane) * OUTn + 2] = hnKeep * outW[2 * Hn + jgl];
        __syncthreads();
        if (tid < 32 * OUTn) {
            int b = tid / OUTn, o = tid - b * OUTn;
            float v = 0.f;
#pragma unroll
            for (int jw = 0; jw < 16; jw++)
                v += s_a[(jw * 32 + b) * OUTn + o];
            hpOut[b * OUTn + o] = v;
        }
    }
}

// ---------------- the persistent kernel ----------------
__global__ void __launch_bounds__(NTHR, 1) orbit_kernel(Params P)
{
    extern __shared__ float smem[];
    float* s_w    = smem;
    float* s_a    = smem + SW_FLOATS;
    float* s_bias = smem + SB_OFF;

    const int tid  = threadIdx.x;
    const int bid  = blockIdx.x;
    const int gtid = bid * NTHR + tid;
    const int gstr = NBLK * NTHR;

    // ===== Phase 0: zero encoder states AND reset group-barrier state =====
    {
        float* h0 = &g_h[0][0][0][0];
        float* c0 = &g_c[0][0][0];
        for (int e = gtid; e < 4 * Bn * Hn; e += gstr) { h0[e] = 0.f; c0[e] = 0.f; }
        for (int e = gtid; e < 16 * 32; e += gstr) { g_gcnt[e] = 0u; g_ggen[e] = 0u; }
    }
    gbar();

    // ===== Encoder: group of 8 blocks covers (dir, 64-b tile); block owns 16 j =====
    const int dir = bid >> 6;
    const int jbE = bid & 7;
    const int b0E = ((bid >> 3) & 7) * 64;
    const int j0E = jbE * 16;
    const int grp = bid >> 3;            // 0..15 (same partition for enc & dec)
    unsigned done = 0;                   // this block's completed group rounds

#pragma unroll 1
    for (int layer = 0; layer < 2; layer++) {
        int st  = layer * 2 + dir;
        if (bid < 128) {
            int kin = layer ? 2 * Hn : INn;
            pack_cell(s_w, s_bias, P.wih[st], P.whh[st], P.bih[st], P.bhh[st], kin, j0E, 0, 0);
        }
        __syncthreads();
#pragma unroll 1
        for (int s = 0; s < Tn; s++) {
            int cur = s & 1, nxt = cur ^ 1;
            if (bid < 128) {
                int t = dir ? (Tn - 1 - s) : s;
                if (layer == 0) {
                    cell_tile<64, 2>(s_w, s_a, s_bias, b0E, j0E,
                        P.x, (long)Tn * INn, (long)t * INn, INn, 0,
                        &g_h[cur][st][0][0], &g_h[nxt][st][0][0], &g_c[st][0][0],
                        g_y0 + (size_t)t * Bn * 2 * Hn + dir * Hn, 2 * Hn,
                        grp, done, false, 0, nullptr, nullptr, nullptr, nullptr, nullptr);
                } else {
                    cell_tile<64, 2>(s_w, s_a, s_bias, b0E, j0E,
                        g_y0 + (size_t)t * Bn * 2 * Hn, (long)(2 * Hn), 0L, 2 * Hn, 0,
                        &g_h[cur][st][0][0], &g_h[nxt][st][0][0], &g_c[st][0][0],
                        nullptr, 0,
                        grp, done, false, 0, nullptr, nullptr, nullptr, nullptr, nullptr);
                }
                gb_arrive(grp); done++;
            }
        }
        gbar();                       // layer boundary: y0 / final states global
    }

    // ===== Bridge: h_dec/c_dec (final enc states in buffer 0) =====
    {
        for (int idx = gtid; idx < (1 << 18); idx += gstr) {
            int j   = idx & (Hn - 1);
            int b   = (idx >> 7) & (Bn - 1);
            int l   = (idx >> 16) & 1;
            int typ = idx >> 17;
            const float* W    = typ ? P.brc_W : P.brh_W;
            const float* bias = typ ? P.brc_b : P.brh_b;
            const float* srcF = typ ? &g_c[2 * l][0][0] : &g_h[0][2 * l][0][0];
            const float* srcB = typ ? &g_c[2 * l + 1][0][0] : &g_h[0][2 * l + 1][0][0];
            const float* wr = &W[j * 2 * Hn];
            float acc = bias[j];
#pragma unroll 4
            for (int k = 0; k < Hn; k++) acc += srcF[b * Hn + k] * wr[k];
#pragma unroll 4
            for (int k = 0; k < Hn; k++) acc += srcB[b * Hn + k] * wr[Hn + k];
            if (typ) g_c[4 + l][b][j] = acc;
            else     g_h[0][4 + l][b][j] = acc;
        }
    }
    gbar();

    // ===== Decoder: group of 8 blocks covers 32-b tile; block owns 16 j =====
    // 2 rounds per step: cell0 (dep = xin partial-sum), cell1+head-partials.
    const int btD = bid >> 3;          // 0..15
    const int jbD = bid & 7;
    const int b0D = btD * 32;
    const int j0D = jbD * 16;

    if (bid < 128) {
        pack_cell(s_w, s_bias, P.wih[4], P.whh[4], P.bih[4], P.bhh[4], OUTn, j0D, 0,   0);
        pack_cell(s_w, s_bias, P.wih[5], P.whh[5], P.bih[5], P.bhh[5], Hn,   j0D, 131, 1);
    }
    __syncthreads();

#pragma unroll 1
    for (int s = 0; s < HORn; s++) {
        int cur = s & 1, nxt = cur ^ 1;
        if (bid < 128) {
            // cell 0: indep = own h4; dep = xin (sum of step s-1's head partials)
            int xmode = (s == 0) ? 2 : 1;
            const float* xv = (s == 0) ? P.start : P.out_b;
            float* pprev = (jbD == 0 && s > 0)
                         ? P.out + (size_t)(s - 1) * OUTn : nullptr;
            cell_tile<32, 1>(s_w, s_a, s_bias, b0D, j0D,
                P.start, (long)0, 0L, OUTn, 0,
                &g_h[cur][4][0][0], &g_h[nxt][4][0][0], &g_c[4][0][0], nullptr, 0,
                grp, done, true,
                xmode, &g_hp[s & 1][btD][0][0][0], xv, pprev, nullptr, nullptr);
            gb_arrive(grp); done++;

            // cell 1: indep = own h5; dep = cell0's new h4; fused head partials
            cell_tile<32, 1>(s_w, s_a, s_bias + 64, b0D, j0D,
                &g_h[nxt][4][0][0], (long)Hn, 0L, Hn, 131,
                &g_h[cur][5][0][0], &g_h[nxt][5][0][0], &g_c[5][0][0], nullptr, 0,
                grp, done, true,
                0, nullptr, nullptr, nullptr,
                &g_hp[(s + 1) & 1][btD][jbD][0][0], P.out_W);
            gb_arrive(grp); done++;
        }
    }

    // tail: write the last prediction (never consumed as xin)
    if (bid < 128) {
        gb_wait(grp, done);
        if (jbD == 0 && tid < 32 * OUTn) {
            int b = tid / OUTn, o = tid - b * OUTn;
            float v = P.out_b[o];
#pragma unroll
            for (int jb = 0; jb < 8; jb++)
                v += g_hp[HORn & 1][btD][jb][b][o];
            P.out[(size_t)(b0D + b) * HORn * OUTn + (size_t)(HORn - 1) * OUTn + o] = v;
        }
    }
}

// ---------------- launch ----------------
extern "C" void kernel_launch(void* const* d_in, const int* in_sizes, int n_in,
                              void* d_out, int out_size)
{
    (void)in_sizes; (void)n_in; (void)out_size;
    Params P;
    P.x = (const float*)d_in[0];
    const int base[6] = {1, 5, 9, 13, 21, 25};   // e0f,e0b,e1f,e1b,d0,d1
    for (int i = 0; i < 6; i++) {
        P.wih[i] = (const float*)d_in[base[i] + 0];
        P.whh[i] = (const float*)d_in[base[i] + 1];
        P.bih[i] = (const float*)d_in[base[i] + 2];
        P.bhh[i] = (const float*)d_in[base[i] + 3];
    }
    P.brh_W = (const float*)d_in[17];
    P.brh_b = (const float*)d_in[18];
    P.brc_W = (const float*)d_in[19];
    P.brc_b = (const float*)d_in[20];
    P.out_W = (const float*)d_in[29];
    P.out_b = (const float*)d_in[30];
    P.start = (const float*)d_in[31];
    P.out   = (float*)d_out;

    cudaFuncSetAttribute(orbit_kernel, cudaFuncAttributeMaxDynamicSharedMemorySize,
                         SMEM_BYTES);
    orbit_kernel<<<NBLK, NTHR, SMEM_BYTES>>>(P);
}

// round 13
// speedup vs baseline: 2.0986x; 1.2793x over previous
#include <cuda_runtime.h>

#define Tn   720
#define Bn   512
#define INn  6
#define Hn   128
#define OUTn 3
#define HORn 360
#define NBLK 148
#define NTHR 256
#define CHK  128
#define STRD 132   // [b][kk] staging stride: 33*16B -> conflict-free LDS.128

typedef unsigned long long ull;

struct Params {
    const float* x;
    const float* wih[6];   // e0f,e0b,e1f,e1b,d0,d1
    const float* whh[6];
    const float* bih[6];
    const float* bhh[6];
    const float* brh_W; const float* brh_b;
    const float* brc_W; const float* brc_b;
    const float* out_W; const float* out_b;
    const float* start;
    float* out;
};

// ---------------- scratch (device globals; no allocation allowed) ----------------
__device__ float g_y0[(size_t)Tn * Bn * 2 * Hn];      // encoder layer0 outputs [t][b][256]
__device__ float g_h[2][6][Bn][Hn];                   // double-buffered hidden state
__device__ float g_c[6][Bn][Hn];                      // cell state (in-place)
__device__ float g_hp[2][16][8][32][OUTn];            // decoder head partials [parity][grp][jb][b][o]
__device__ unsigned g_barcnt = 0;
__device__ unsigned g_bargen = 0;
__device__ unsigned g_gcnt[16 * 32];                  // monotonic arrival counts, 128B apart
__device__ unsigned g_ggen[16 * 32];                  // published completed-round counts

// ---------------- shared-memory layout (dynamic, ~167KB) ----------------
#define SW_FLOATS (387 * 64)            // weights [row][jloc*4+gate], 16 j per block
#define SA_FLOATS (64 * STRD)           // one staging buffer: 64 b x 128 kk (+pad)
#define SB_OFF    (SW_FLOATS + 2 * SA_FLOATS)
#define SMEM_BYTES ((SB_OFF + 128) * 4)

// ---------------- cp.async helpers ----------------
__device__ __forceinline__ void cp16(unsigned saddr, const float* g) {
    asm volatile("cp.async.ca.shared.global [%0], [%1], 16;" :: "r"(saddr), "l"(g));
}
#define CP_COMMIT() asm volatile("cp.async.commit_group;" ::: "memory")
#define CP_WAIT0()  asm volatile("cp.async.wait_group 0;" ::: "memory")

// ---------------- full grid barrier (phase boundaries only) ----------------
__device__ __forceinline__ void gbar() {
    __syncthreads();
    if (threadIdx.x == 0) {
        volatile unsigned* vg = &g_bargen;
        unsigned gen = *vg;
        __threadfence();
        if (atomicAdd(&g_barcnt, 1u) == NBLK - 1) {
            g_barcnt = 0;
            __threadfence();
            *vg = gen + 1;
        } else {
            while (*vg == gen) { __nanosleep(32); }
        }
        __threadfence();
    }
    __syncthreads();
}

// ---------------- split 8-block group barrier (monotonic rounds) ----------------
// Counters RESET each launch in Phase 0 (graph-replay determinism).
__device__ __forceinline__ void gb_arrive(int g) {
    __syncthreads();                           // all epilogue stores issued
    if (threadIdx.x == 0) {
        __threadfence();                       // release h/partial stores
        unsigned old = atomicAdd(&g_gcnt[g * 32], 1u);
        if (((old + 1) & 7u) == 0u) {          // 8th arrival of this round
            __threadfence();
            *(volatile unsigned*)&g_ggen[g * 32] = (old + 1) >> 3;
        }
    }
}
__device__ __forceinline__ void gb_wait(int g, unsigned target) {
    if (threadIdx.x == 0) {
        volatile unsigned* vg = &g_ggen[g * 32];
        while (*vg < target) { __nanosleep(20); }
        __threadfence();                       // acquire: invalidate L1
    }
    __syncthreads();
}

// ---------------- fast activations ----------------
__device__ __forceinline__ float sigf(float x) {
    return __fdividef(1.f, 1.f + __expf(-x));
}
__device__ __forceinline__ float tanhfast(float x) {
    return 1.f - __fdividef(2.f, __expf(2.f * x) + 1.f);
}

// ---------------- per-phase weight packing into smem ----------------
__device__ void pack_cell(float* __restrict__ s_w, float* __restrict__ s_bias,
                          const float* __restrict__ wih, const float* __restrict__ whh,
                          const float* __restrict__ bih, const float* __restrict__ bhh,
                          int Kin, int j0, int rowBase, int biasSlot)
{
    int total = (Kin + Hn) * 64;
    for (int e = threadIdx.x; e < total; e += NTHR) {
        int row = e >> 6, c = e & 63;
        int j = j0 + (c >> 2), g = c & 3;
        float v = (row < Kin) ? wih[(g * Hn + j) * Kin + row]
                              : whh[(g * Hn + j) * Hn + (row - Kin)];
        s_w[(size_t)(rowBase + row) * 64 + c] = v;
    }
    for (int e = threadIdx.x; e < 64; e += NTHR) {
        int j = j0 + (e >> 2), g = e & 3;
        s_bias[biasSlot * 64 + e] = bih[g * Hn + j] + bhh[g * Hn + j];
    }
}

struct Chunk { const float* src; long str; int kc; int wrow; };

// ---------------- fused LSTM cell tile ----------------
// Tile: BT b-rows x 16 j's with 256 threads, 8 warps. lane = b, warp = j-PAIR
// (two adjacent j per thread; their packed gate columns are contiguous 32B).
// Each thread owns NB b x 2 j. Activation smem reads are shared across the
// 2 j (halves crossbar traffic vs 1 j/thread); weight reads stay broadcast.
template<int BT, int NB>
__device__ void cell_tile(float* __restrict__ s_w, float* __restrict__ s_a,
                          const float* __restrict__ s_bias,
                          int b0, int j0g,
                          const float* __restrict__ A, long aStr, long aOff, int Kin, int rowBase,
                          const float* __restrict__ hsrc, float* __restrict__ hdst,
                          float* __restrict__ cst, float* __restrict__ yout, int yStr,
                          int g, unsigned waitRound, bool hFirst,
                          int xinMode, const float* __restrict__ hpIn,
                          const float* __restrict__ xvec, float* __restrict__ poutPrev,
                          float* __restrict__ hpOut, const float* __restrict__ outW)
{
    const int tid  = threadIdx.x;
    const int lane = tid & 31;
    const int jq   = tid >> 5;            // j-pair index 0..7
    const int j0l  = jq * 2;              // first of this thread's two j (local)
    const int jgl  = j0g + j0l;           // global j of first
    const unsigned sa0 = (unsigned)__cvta_generic_to_shared(s_a);

    ull accL[NB][2], accH[NB][2];         // [b-block][which-j]: packed (i,f),(g,o)
    {
        ulonglong2 bj0 = *(const ulonglong2*)&s_bias[jq * 8];
        ulonglong2 bj1 = *(const ulonglong2*)&s_bias[jq * 8 + 4];
#pragma unroll
        for (int i = 0; i < NB; i++) {
            accL[i][0] = bj0.x; accH[i][0] = bj0.y;
            accL[i][1] = bj1.x; accH[i][1] = bj1.y;
        }
    }

    // ---- build chunk list, dependent chunk last ----
    Chunk ch[3]; int nch = 0;
    if (hFirst) {
        ch[nch++] = { hsrc + (long)b0 * Hn, (long)Hn, CHK, rowBase + Kin };
        ch[nch++] = { A + (long)b0 * aStr + aOff, aStr,
                      (Kin < CHK) ? Kin : CHK, rowBase };
    } else {
        for (int k0 = 0; k0 < Kin; k0 += CHK) {
            int kc = (Kin - k0 < CHK) ? (Kin - k0) : CHK;
            ch[nch].src = A + (long)b0 * aStr + aOff + k0;
            ch[nch].str = aStr; ch[nch].kc = kc; ch[nch].wrow = rowBase + k0;
            nch++;
        }
        ch[nch++] = { hsrc + (long)b0 * Hn, (long)Hn, CHK, rowBase + Kin };
    }

    auto stage_async = [&](const Chunk& c, int buf) {
#pragma unroll
        for (int u = 0; u < BT * 32 / NTHR; u++) {
            int q = tid + u * NTHR;       // quad index: b = q>>5, kq = q&31
            int b = q >> 5, kq = q & 31;
            cp16(sa0 + (unsigned)(buf * SA_FLOATS + b * STRD + kq * 4) * 4u,
                 c.src + (long)b * c.str + kq * 4);
        }
        CP_COMMIT();
    };
    // scalar staging for small chunks (K = 6 or 3); handles xin modes
    auto stage_small = [&](const Chunk& c, int buf) {
        if (xinMode == 2) {
            for (int idx = tid; idx < BT * c.kc; idx += NTHR) {
                int b = idx / c.kc, kk = idx - b * c.kc;
                s_a[buf * SA_FLOATS + b * STRD + kk] = xvec[kk];
            }
        } else if (xinMode == 1) {
            for (int idx = tid; idx < BT * OUTn; idx += NTHR) {
                int b = idx / OUTn, o = idx - b * OUTn;
                float v = xvec[o];
#pragma unroll
                for (int jb = 0; jb < 8; jb++)
                    v += hpIn[(jb * 32 + b) * OUTn + o];
                s_a[buf * SA_FLOATS + b * STRD + o] = v;
                if (poutPrev)
                    poutPrev[(size_t)(b0 + b) * HORn * OUTn + o] = v;
            }
        } else {
            for (int idx = tid; idx < BT * c.kc; idx += NTHR) {
                int b = idx / c.kc, kk = idx - b * c.kc;
                s_a[buf * SA_FLOATS + b * STRD + kk] = c.src[(long)b * c.str + kk];
            }
        }
    };

    // chunk 0 into buffer 0 (always independent — no wait needed)
    if (ch[0].kc == CHK) { stage_async(ch[0], 0); CP_WAIT0(); }
    else                 { stage_small(ch[0], 0); }
    __syncthreads();

#pragma unroll 1
    for (int i = 0; i < nch; i++) {
        if (i + 1 < nch) {
            if (i + 1 == nch - 1) gb_wait(g, waitRound);   // dep chunk: wait first
            if (ch[i + 1].kc == CHK) stage_async(ch[i + 1], (i + 1) & 1);
            else                     stage_small(ch[i + 1], (i + 1) & 1);
        }

        const int kc = ch[i].kc;
        const float* wp = s_w + (size_t)ch[i].wrow * 64 + jq * 8;
        const float* ab = s_a + (i & 1) * SA_FLOATS;
        if (kc == CHK) {
#pragma unroll 2
            for (int kq = 0; kq < CHK; kq += 4) {
                float4 av[NB];
#pragma unroll
                for (int n = 0; n < NB; n++)
                    av[n] = *(const float4*)&ab[(lane + 32 * n) * STRD + kq];
#pragma unroll
                for (int t = 0; t < 4; t++) {
                    ulonglong2 w0 = *(const ulonglong2*)(wp + (size_t)(kq + t) * 64);
                    ulonglong2 w1 = *(const ulonglong2*)(wp + (size_t)(kq + t) * 64 + 4);
#pragma unroll
                    for (int n = 0; n < NB; n++) {
                        float a = (t == 0) ? av[n].x : (t == 1) ? av[n].y
                                : (t == 2) ? av[n].z : av[n].w;
                        ull a2; asm("mov.b64 %0,{%1,%1};" : "=l"(a2) : "f"(a));
                        asm("fma.rn.f32x2 %0,%1,%2,%0;" : "+l"(accL[n][0]) : "l"(a2), "l"(w0.x));
                        asm("fma.rn.f32x2 %0,%1,%2,%0;" : "+l"(accH[n][0]) : "l"(a2), "l"(w0.y));
                        asm("fma.rn.f32x2 %0,%1,%2,%0;" : "+l"(accL[n][1]) : "l"(a2), "l"(w1.x));
                        asm("fma.rn.f32x2 %0,%1,%2,%0;" : "+l"(accH[n][1]) : "l"(a2), "l"(w1.y));
                    }
                }
            }
        } else {
            for (int kk = 0; kk < kc; kk++) {
                ulonglong2 w0 = *(const ulonglong2*)(wp + (size_t)kk * 64);
                ulonglong2 w1 = *(const ulonglong2*)(wp + (size_t)kk * 64 + 4);
#pragma unroll
                for (int n = 0; n < NB; n++) {
                    float a = ab[(lane + 32 * n) * STRD + kk];
                    ull a2; asm("mov.b64 %0,{%1,%1};" : "=l"(a2) : "f"(a));
                    asm("fma.rn.f32x2 %0,%1,%2,%0;" : "+l"(accL[n][0]) : "l"(a2), "l"(w0.x));
                    asm("fma.rn.f32x2 %0,%1,%2,%0;" : "+l"(accH[n][0]) : "l"(a2), "l"(w0.y));
                    asm("fma.rn.f32x2 %0,%1,%2,%0;" : "+l"(accL[n][1]) : "l"(a2), "l"(w1.x));
                    asm("fma.rn.f32x2 %0,%1,%2,%0;" : "+l"(accH[n][1]) : "l"(a2), "l"(w1.y));
                }
            }
        }

        if (i + 1 < nch) { CP_WAIT0(); __syncthreads(); }
    }

    // gate update — thread exclusively owns (b, jgl) and (b, jgl+1): float2 path
    float hnKeep[2] = {0.f, 0.f};
#pragma unroll
    for (int i = 0; i < NB; i++) {
        int b = b0 + lane + 32 * i;
        long ci = (long)b * Hn + jgl;
        float2 cold = *(float2*)&cst[ci];
        float gi0, gf0, gg0, go0, gi1, gf1, gg1, go1;
        asm("mov.b64 {%0,%1},%2;" : "=f"(gi0), "=f"(gf0) : "l"(accL[i][0]));
        asm("mov.b64 {%0,%1},%2;" : "=f"(gg0), "=f"(go0) : "l"(accH[i][0]));
        asm("mov.b64 {%0,%1},%2;" : "=f"(gi1), "=f"(gf1) : "l"(accL[i][1]));
        asm("mov.b64 {%0,%1},%2;" : "=f"(gg1), "=f"(go1) : "l"(accH[i][1]));
        float2 cn, hn;
        cn.x = sigf(gf0) * cold.x + sigf(gi0) * tanhfast(gg0);
        cn.y = sigf(gf1) * cold.y + sigf(gi1) * tanhfast(gg1);
        hn.x = sigf(go0) * tanhfast(cn.x);
        hn.y = sigf(go1) * tanhfast(cn.y);
        *(float2*)&cst[ci]  = cn;
        *(float2*)&hdst[ci] = hn;
        hnKeep[0] = hn.x; hnKeep[1] = hn.y;
        if (yout) *(float2*)&yout[(long)b * yStr + jgl] = hn;
    }

    // head partials (decoder cell1 only; NB==1): block's 16 j -> [32b][3o]
    if (hpOut) {
        __syncthreads();                       // s_a buf0 free for reduction
#pragma unroll
        for (int jj = 0; jj < 2; jj++) {
            int jl = j0l + jj;
            s_a[(jl * 32 + lane) * OUTn + 0] = hnKeep[jj] * outW[jgl + jj];
            s_a[(jl * 32 + lane) * OUTn + 1] = hnKeep[jj] * outW[Hn + jgl + jj];
            s_a[(jl * 32 + lane) * OUTn + 2] = hnKeep[jj] * outW[2 * Hn + jgl + jj];
        }
        __syncthreads();
        if (tid < 32 * OUTn) {
            int b = tid / OUTn, o = tid - b * OUTn;
            float v = 0.f;
#pragma unroll
            for (int jw = 0; jw < 16; jw++)
                v += s_a[(jw * 32 + b) * OUTn + o];
            hpOut[b * OUTn + o] = v;
        }
    }
}

// ---------------- the persistent kernel ----------------
__global__ void __launch_bounds__(NTHR, 1) orbit_kernel(Params P)
{
    extern __shared__ float smem[];
    float* s_w    = smem;
    float* s_a    = smem + SW_FLOATS;
    float* s_bias = smem + SB_OFF;

    const int tid  = threadIdx.x;
    const int bid  = blockIdx.x;
    const int gtid = bid * NTHR + tid;
    const int gstr = NBLK * NTHR;

    // ===== Phase 0: zero encoder states AND reset group-barrier state =====
    {
        float* h0 = &g_h[0][0][0][0];
        float* c0 = &g_c[0][0][0];
        for (int e = gtid; e < 4 * Bn * Hn; e += gstr) { h0[e] = 0.f; c0[e] = 0.f; }
        for (int e = gtid; e < 16 * 32; e += gstr) { g_gcnt[e] = 0u; g_ggen[e] = 0u; }
    }
    gbar();

    // ===== Encoder: group of 8 blocks covers (dir, 64-b tile); block owns 16 j =====
    const int dir = bid >> 6;
    const int jbE = bid & 7;
    const int b0E = ((bid >> 3) & 7) * 64;
    const int j0E = jbE * 16;
    const int grp = bid >> 3;            // 0..15 (same partition for enc & dec)
    unsigned done = 0;                   // this block's completed group rounds

#pragma unroll 1
    for (int layer = 0; layer < 2; layer++) {
        int st  = layer * 2 + dir;
        if (bid < 128) {
            int kin = layer ? 2 * Hn : INn;
            pack_cell(s_w, s_bias, P.wih[st], P.whh[st], P.bih[st], P.bhh[st], kin, j0E, 0, 0);
        }
        __syncthreads();
#pragma unroll 1
        for (int s = 0; s < Tn; s++) {
            int cur = s & 1, nxt = cur ^ 1;
            if (bid < 128) {
                int t = dir ? (Tn - 1 - s) : s;
                if (layer == 0) {
                    cell_tile<64, 2>(s_w, s_a, s_bias, b0E, j0E,
                        P.x, (long)Tn * INn, (long)t * INn, INn, 0,
                        &g_h[cur][st][0][0], &g_h[nxt][st][0][0], &g_c[st][0][0],
                        g_y0 + (size_t)t * Bn * 2 * Hn + dir * Hn, 2 * Hn,
                        grp, done, false, 0, nullptr, nullptr, nullptr, nullptr, nullptr);
                } else {
                    cell_tile<64, 2>(s_w, s_a, s_bias, b0E, j0E,
                        g_y0 + (size_t)t * Bn * 2 * Hn, (long)(2 * Hn), 0L, 2 * Hn, 0,
                        &g_h[cur][st][0][0], &g_h[nxt][st][0][0], &g_c[st][0][0],
                        nullptr, 0,
                        grp, done, false, 0, nullptr, nullptr, nullptr, nullptr, nullptr);
                }
                gb_arrive(grp); done++;
            }
        }
        gbar();                       // layer boundary: y0 / final states global
    }

    // ===== Bridge: h_dec/c_dec (final enc states in buffer 0) =====
    {
        for (int idx = gtid; idx < (1 << 18); idx += gstr) {
            int j   = idx & (Hn - 1);
            int b   = (idx >> 7) & (Bn - 1);
            int l   = (idx >> 16) & 1;
            int typ = idx >> 17;
            const float* W    = typ ? P.brc_W : P.brh_W;
            const float* bias = typ ? P.brc_b : P.brh_b;
            const float* srcF = typ ? &g_c[2 * l][0][0] : &g_h[0][2 * l][0][0];
            const float* srcB = typ ? &g_c[2 * l + 1][0][0] : &g_h[0][2 * l + 1][0][0];
            const float* wr = &W[j * 2 * Hn];
            float acc = bias[j];
#pragma unroll 4
            for (int k = 0; k < Hn; k++) acc += srcF[b * Hn + k] * wr[k];
#pragma unroll 4
            for (int k = 0; k < Hn; k++) acc += srcB[b * Hn + k] * wr[Hn + k];
            if (typ) g_c[4 + l][b][j] = acc;
            else     g_h[0][4 + l][b][j] = acc;
        }
    }
    gbar();

    // ===== Decoder: group of 8 blocks covers 32-b tile; block owns 16 j =====
    // 2 rounds per step: cell0 (dep = xin partial-sum), cell1+head-partials.
    const int btD = bid >> 3;          // 0..15
    const int jbD = bid & 7;
    const int b0D = btD * 32;
    const int j0D = jbD * 16;

    if (bid < 128) {
        pack_cell(s_w, s_bias, P.wih[4], P.whh[4], P.bih[4], P.bhh[4], OUTn, j0D, 0,   0);
        pack_cell(s_w, s_bias, P.wih[5], P.whh[5], P.bih[5], P.bhh[5], Hn,   j0D, 131, 1);
    }
    __syncthreads();

#pragma unroll 1
    for (int s = 0; s < HORn; s++) {
        int cur = s & 1, nxt = cur ^ 1;
        if (bid < 128) {
            // cell 0: indep = own h4; dep = xin (sum of step s-1's head partials)
            int xmode = (s == 0) ? 2 : 1;
            const float* xv = (s == 0) ? P.start : P.out_b;
            float* pprev = (jbD == 0 && s > 0)
                         ? P.out + (size_t)(s - 1) * OUTn : nullptr;
            cell_tile<32, 1>(s_w, s_a, s_bias, b0D, j0D,
                P.start, (long)0, 0L, OUTn, 0,
                &g_h[cur][4][0][0], &g_h[nxt][4][0][0], &g_c[4][0][0], nullptr, 0,
                grp, done, true,
                xmode, &g_hp[s & 1][btD][0][0][0], xv, pprev, nullptr, nullptr);
            gb_arrive(grp); done++;

            // cell 1: indep = own h5; dep = cell0's new h4; fused head partials
            cell_tile<32, 1>(s_w, s_a, s_bias + 64, b0D, j0D,
                &g_h[nxt][4][0][0], (long)Hn, 0L, Hn, 131,
                &g_h[cur][5][0][0], &g_h[nxt][5][0][0], &g_c[5][0][0], nullptr, 0,
                grp, done, true,
                0, nullptr, nullptr, nullptr,
                &g_hp[(s + 1) & 1][btD][jbD][0][0], P.out_W);
            gb_arrive(grp); done++;
        }
    }

    // tail: write the last prediction (never consumed as xin)
    if (bid < 128) {
        gb_wait(grp, done);
        if (jbD == 0 && tid < 32 * OUTn) {
            int b = tid / OUTn, o = tid - b * OUTn;
            float v = P.out_b[o];
#pragma unroll
            for (int jb = 0; jb < 8; jb++)
                v += g_hp[HORn & 1][btD][jb][b][o];
            P.out[(size_t)(b0D + b) * HORn * OUTn + (size_t)(HORn - 1) * OUTn + o] = v;
        }
    }
}

// ---------------- launch ----------------
extern "C" void kernel_launch(void* const* d_in, const int* in_sizes, int n_in,
                              void* d_out, int out_size)
{
    (void)in_sizes; (void)n_in; (void)out_size;
    Params P;
    P.x = (const float*)d_in[0];
    const int base[6] = {1, 5, 9, 13, 21, 25};   // e0f,e0b,e1f,e1b,d0,d1
    for (int i = 0; i < 6; i++) {
        P.wih[i] = (const float*)d_in[base[i] + 0];
        P.whh[i] = (const float*)d_in[base[i] + 1];
        P.bih[i] = (const float*)d_in[base[i] + 2];
        P.bhh[i] = (const float*)d_in[base[i] + 3];
    }
    P.brh_W = (const float*)d_in[17];
    P.brh_b = (const float*)d_in[18];
    P.brc_W = (const float*)d_in[19];
    P.brc_b = (const float*)d_in[20];
    P.out_W = (const float*)d_in[29];
    P.out_b = (const float*)d_in[30];
    P.start = (const float*)d_in[31];
    P.out   = (float*)d_out;

    cudaFuncSetAttribute(orbit_kernel, cudaFuncAttributeMaxDynamicSharedMemorySize,
                         SMEM_BYTES);
    orbit_kernel<<<NBLK, NTHR, SMEM_BYTES>>>(P);
}